// round 1
// baseline (speedup 1.0000x reference)
#include <cuda_runtime.h>
#include <cuda_bf16.h>

// ---------------------------------------------------------------------------
// Model_2 : FC -> graph conv (threshold adjacency) -> conv1d x3 -> FC -> logsoftmax
// B=64, N=750, F=8, NF=250
// ---------------------------------------------------------------------------

#define INV_BN 0.9999950000374997f   // 1/sqrt(1 + 1e-5)

// Scratch (device globals; no dynamic allocation allowed)
__device__ float g_xcat[64 * 1000];         // concat [s(250) | g(750)] per batch
__device__ float g_dn[64 * 750];            // D^{-1/2}
__device__ float g_pool1[64 * 32 * 500];    // after conv1+bn+relu+pool
__device__ float g_pool2[64 * 64 * 250];    // after conv2+bn+relu+pool
__device__ float g_part3[8 * 64 * 128];     // conv3 K-split partials [ks][b][oc]

// ---------------------------------------------------------------------------
// K1: s = relu((x_sample @ W1 + b1) * inv * gl + bl)  -> g_xcat[b][0:250]
// ---------------------------------------------------------------------------
__global__ void k_lin1(const float* __restrict__ xs, const float* __restrict__ W1,
                       const float* __restrict__ b1, const float* __restrict__ gl,
                       const float* __restrict__ bl) {
    int b = blockIdx.x;
    __shared__ float xrow[250];
    int t = threadIdx.x;
    if (t < 250) xrow[t] = xs[b * 250 + t];
    __syncthreads();
    if (t < 250) {
        float acc = 0.f;
        #pragma unroll 5
        for (int k = 0; k < 250; k++) acc = fmaf(xrow[k], W1[k * 250 + t], acc);
        float v = (acc + b1[t]) * (INV_BN * gl[t]) + bl[t];
        g_xcat[b * 1000 + t] = fmaxf(v, 0.f);
    }
}

// ---------------------------------------------------------------------------
// K2a: degrees -> dn = rsqrt(count of j with (d_i-d_j)^2 < 0.01)
// grid (64 batches, 2 halves), 384 threads
// ---------------------------------------------------------------------------
__global__ void k_deg(const float* __restrict__ xg) {
    int b = blockIdx.x, h = blockIdx.y;
    __shared__ float d[750];
    int t = threadIdx.x;
    for (int i = t; i < 750; i += 384) d[i] = xg[b * 6000 + i * 8];
    __syncthreads();
    if (t < 375) {
        int i = h * 375 + t;
        float di = d[i];
        float cnt = 0.f;
        for (int j = 0; j < 750; j++) {
            float diff = di - d[j];
            cnt += (diff * diff < 0.01f) ? 1.f : 0.f;   // exact same fp32 predicate as ref
        }
        g_dn[b * 750 + i] = rsqrtf(cnt);
    }
}

// ---------------------------------------------------------------------------
// K2b: y = x_graph @ Wg ; h = dn_i * sum_j mask*dn_j*y[j] + bg ; bn+relu ; mean_f
//      -> g_xcat[b][250 + i]
// grid (64, 2), 384 threads
// ---------------------------------------------------------------------------
__global__ void k_gsum(const float* __restrict__ xg, const float* __restrict__ Wg,
                       const float* __restrict__ bg, const float* __restrict__ g1,
                       const float* __restrict__ be1) {
    int b = blockIdx.x, h = blockIdx.y;
    __shared__ float d[750];
    __shared__ float dn[750];
    __shared__ float4 y4[1500];   // y[j][0:4], y[j][4:8]
    __shared__ float wg[64];
    __shared__ float bgs[8];
    int t = threadIdx.x;
    if (t < 64) wg[t] = Wg[t];
    if (t < 8)  bgs[t] = bg[t];
    for (int i = t; i < 750; i += 384) {
        d[i]  = xg[b * 6000 + i * 8];
        dn[i] = g_dn[b * 750 + i];
    }
    __syncthreads();
    for (int i = t; i < 750; i += 384) {
        const float4* xp = reinterpret_cast<const float4*>(xg + b * 6000 + i * 8);
        float4 a = xp[0], c = xp[1];
        float xv[8] = {a.x, a.y, a.z, a.w, c.x, c.y, c.z, c.w};
        float yv[8];
        #pragma unroll
        for (int f = 0; f < 8; f++) {
            float s = 0.f;
            #pragma unroll
            for (int fp = 0; fp < 8; fp++) s = fmaf(xv[fp], wg[fp * 8 + f], s);
            yv[f] = s;
        }
        y4[2 * i]     = make_float4(yv[0], yv[1], yv[2], yv[3]);
        y4[2 * i + 1] = make_float4(yv[4], yv[5], yv[6], yv[7]);
    }
    __syncthreads();
    if (t < 375) {
        int i = h * 375 + t;
        float di = d[i];
        float a0 = 0, a1 = 0, a2 = 0, a3 = 0, a4 = 0, a5 = 0, a6 = 0, a7 = 0;
        for (int j = 0; j < 750; j++) {
            float diff = di - d[j];
            float w = (diff * diff < 0.01f) ? dn[j] : 0.f;
            float4 ya = y4[2 * j], yb = y4[2 * j + 1];
            a0 = fmaf(w, ya.x, a0); a1 = fmaf(w, ya.y, a1);
            a2 = fmaf(w, ya.z, a2); a3 = fmaf(w, ya.w, a3);
            a4 = fmaf(w, yb.x, a4); a5 = fmaf(w, yb.y, a5);
            a6 = fmaf(w, yb.z, a6); a7 = fmaf(w, yb.w, a7);
        }
        float acc[8] = {a0, a1, a2, a3, a4, a5, a6, a7};
        float dni = dn[i];
        float sc = INV_BN * g1[0];
        float sh = be1[0];
        float gsum = 0.f;
        #pragma unroll
        for (int f = 0; f < 8; f++) {
            float hv = fmaf(dni, acc[f], bgs[f]);
            hv = fmaf(hv, sc, sh);
            gsum += fmaxf(hv, 0.f);
        }
        g_xcat[b * 1000 + 250 + i] = gsum * 0.125f;
    }
}

// ---------------------------------------------------------------------------
// K3: conv1 (1->32, k=5, pad=2) + bn + relu + maxpool2 : [64,1,1000] -> [64,32,500]
// one block per batch, 256 threads
// ---------------------------------------------------------------------------
__global__ void k_conv1(const float* __restrict__ Wc1, const float* __restrict__ bc1,
                        const float* __restrict__ gc1, const float* __restrict__ bec1) {
    int b = blockIdx.x;
    __shared__ float xs[1004];     // padded: xs[i+2] = x[i]
    __shared__ float w[160], bb[32], gg[32], be[32];
    int t = threadIdx.x;
    for (int i = t; i < 1000; i += 256) xs[i + 2] = g_xcat[b * 1000 + i];
    if (t < 2) { xs[t] = 0.f; xs[1002 + t] = 0.f; }
    if (t < 160) w[t] = Wc1[t];
    if (t < 32) { bb[t] = bc1[t]; gg[t] = gc1[t] * INV_BN; be[t] = bec1[t]; }
    __syncthreads();
    for (int idx = t; idx < 32 * 500; idx += 256) {
        int c = idx / 500, p = idx % 500;
        int q = 2 * p;   // window xs[q .. q+5] covers both conv positions
        float v0 = bb[c], v1 = bb[c];
        #pragma unroll
        for (int k = 0; k < 5; k++) {
            float wk = w[c * 5 + k];
            v0 = fmaf(xs[q + k],     wk, v0);
            v1 = fmaf(xs[q + 1 + k], wk, v1);
        }
        v0 = fmaf(v0, gg[c], be[c]);
        v1 = fmaf(v1, gg[c], be[c]);
        g_pool1[(b * 32 + c) * 500 + p] = fmaxf(fmaxf(v0, v1), 0.f);
    }
}

// ---------------------------------------------------------------------------
// K4: conv2 (32->64, k=5, pad=2) + bn + relu + maxpool2 : [64,32,500] -> [64,64,250]
// grid (b=64, ptile=4, ochalf=2), 256 threads
// ---------------------------------------------------------------------------
__global__ void k_conv2(const float* __restrict__ Wc2, const float* __restrict__ bc2,
                        const float* __restrict__ gc2, const float* __restrict__ bec2) {
    int b = blockIdx.x, pt = blockIdx.y, oh = blockIdx.z;
    int p0 = pt * 63;
    int pc = min(63, 250 - p0);          // 63,63,63,61
    int oc0 = oh * 32;
    __shared__ float sx[32][132];        // input slab, conv positions [2*p0-2 .. 2*p0+2*pc+1]
    __shared__ float sw[32][160];        // 32 output channels' weights
    __shared__ float bb[32], gg[32], be[32];
    int t = threadIdx.x;
    int qb = 2 * p0 - 2;
    int nq = 2 * pc + 4;
    for (int i = t; i < 32 * nq; i += 256) {
        int ic = i / nq, ii = i - ic * nq;
        int q = qb + ii;
        sx[ic][ii] = (q >= 0 && q < 500) ? g_pool1[(b * 32 + ic) * 500 + q] : 0.f;
    }
    for (int i = t; i < 32 * 160; i += 256) {
        int o = i >> 7; o = i / 160;     // keep simple
        int j = i - o * 160;
        sw[o][j] = Wc2[(oc0 + o) * 160 + j];
    }
    if (t < 32) { bb[t] = bc2[oc0 + t]; gg[t] = gc2[oc0 + t] * INV_BN; be[t] = bec2[oc0 + t]; }
    __syncthreads();
    for (int idx = t; idx < 32 * pc; idx += 256) {
        int oc = idx / pc, p = idx - oc * pc;
        float a0 = bb[oc], a1 = a0;
        const float* wr = sw[oc];
        #pragma unroll 4
        for (int ic = 0; ic < 32; ic++) {
            const float* xr = &sx[ic][2 * p];
            float x0 = xr[0], x1 = xr[1], x2 = xr[2], x3 = xr[3], x4 = xr[4], x5 = xr[5];
            float w0 = wr[ic*5], w1 = wr[ic*5+1], w2 = wr[ic*5+2], w3 = wr[ic*5+3], w4 = wr[ic*5+4];
            a0 = fmaf(x0,w0,a0); a0 = fmaf(x1,w1,a0); a0 = fmaf(x2,w2,a0);
            a0 = fmaf(x3,w3,a0); a0 = fmaf(x4,w4,a0);
            a1 = fmaf(x1,w0,a1); a1 = fmaf(x2,w1,a1); a1 = fmaf(x3,w2,a1);
            a1 = fmaf(x4,w3,a1); a1 = fmaf(x5,w4,a1);
        }
        a0 = fmaf(a0, gg[oc], be[oc]);
        a1 = fmaf(a1, gg[oc], be[oc]);
        g_pool2[(b * 64 + oc0 + oc) * 250 + p0 + p] = fmaxf(fmaxf(a0, a1), 0.f);
    }
}

// ---------------------------------------------------------------------------
// K5: conv3 as GEMM partials: out[b][oc] = sum_{k<16000} in2[b][k]*Wc3[oc][k]
// grid (ocgroup=16, ksplit=8), 256 threads; each block: 64 b x 8 oc x 2000 k
// ---------------------------------------------------------------------------
__global__ void k_conv3(const float* __restrict__ Wc3) {
    int og = blockIdx.x;     // 0..15
    int ks = blockIdx.y;     // 0..7
    __shared__ float Xs[100][66];   // [k][b], padded
    __shared__ float Ws[8][100];
    int t = threadIdx.x;
    int b = t & 63;
    int o2 = t >> 6;         // 0..3 -> oc pair
    float acc0 = 0.f, acc1 = 0.f;
    int kbase = ks * 2000;
    for (int c = 0; c < 20; c++) {
        int k0 = kbase + c * 100;
        __syncthreads();
        for (int i = t; i < 6400; i += 256) {
            int bb2 = i / 100, kk = i - bb2 * 100;
            Xs[kk][bb2] = g_pool2[bb2 * 16000 + k0 + kk];
        }
        for (int i = t; i < 800; i += 256) {
            int o = i / 100, kk = i - o * 100;
            Ws[o][kk] = Wc3[(og * 8 + o) * 16000 + k0 + kk];
        }
        __syncthreads();
        const float* w0 = Ws[o2 * 2];
        const float* w1 = Ws[o2 * 2 + 1];
        #pragma unroll 4
        for (int k = 0; k < 100; k++) {
            float xv = Xs[k][b];
            acc0 = fmaf(xv, w0[k], acc0);
            acc1 = fmaf(xv, w1[k], acc1);
        }
    }
    int oc = og * 8 + o2 * 2;
    g_part3[(ks * 64 + b) * 128 + oc]     = acc0;
    g_part3[(ks * 64 + b) * 128 + oc + 1] = acc1;
}

// ---------------------------------------------------------------------------
// K6: reduce partials (+bc3), FC 128->64 (+bn relu), FC 64->12, log_softmax
// one block per batch, 128 threads
// ---------------------------------------------------------------------------
__global__ void k_fc(const float* __restrict__ bc3, const float* __restrict__ Wf,
                     const float* __restrict__ bf, const float* __restrict__ gf,
                     const float* __restrict__ bef, const float* __restrict__ Wo,
                     const float* __restrict__ bo, float* __restrict__ out) {
    int b = blockIdx.x;
    int t = threadIdx.x;
    __shared__ float f[128], u[64], o[12];
    {
        float s = bc3[t];
        #pragma unroll
        for (int ks = 0; ks < 8; ks++) s += g_part3[(ks * 64 + b) * 128 + t];
        f[t] = s;
    }
    __syncthreads();
    if (t < 64) {
        float z = bf[t];
        #pragma unroll 8
        for (int k = 0; k < 128; k++) z = fmaf(f[k], Wf[k * 64 + t], z);
        z = z * (INV_BN * gf[t]) + bef[t];
        u[t] = fmaxf(z, 0.f);
    }
    __syncthreads();
    if (t < 12) {
        float z = bo[t];
        #pragma unroll 8
        for (int k = 0; k < 64; k++) z = fmaf(u[k], Wo[k * 12 + t], z);
        o[t] = z;
    }
    __syncthreads();
    if (t < 12) {
        float m = o[0];
        #pragma unroll
        for (int i = 1; i < 12; i++) m = fmaxf(m, o[i]);
        float s = 0.f;
        #pragma unroll
        for (int i = 0; i < 12; i++) s += expf(o[i] - m);
        out[b * 12 + t] = (o[t] - m) - logf(s);
    }
}

// ---------------------------------------------------------------------------
extern "C" void kernel_launch(void* const* d_in, const int* in_sizes, int n_in,
                              void* d_out, int out_size) {
    const float* x_sample = (const float*)d_in[0];
    const float* x_graph  = (const float*)d_in[1];
    const float* W1   = (const float*)d_in[2];
    const float* b1   = (const float*)d_in[3];
    const float* gl   = (const float*)d_in[4];
    const float* bl   = (const float*)d_in[5];
    const float* Wg   = (const float*)d_in[6];
    const float* bg   = (const float*)d_in[7];
    const float* g1   = (const float*)d_in[8];
    const float* be1  = (const float*)d_in[9];
    const float* Wc1  = (const float*)d_in[10];
    const float* bc1  = (const float*)d_in[11];
    const float* gc1  = (const float*)d_in[12];
    const float* bec1 = (const float*)d_in[13];
    const float* Wc2  = (const float*)d_in[14];
    const float* bc2  = (const float*)d_in[15];
    const float* gc2  = (const float*)d_in[16];
    const float* bec2 = (const float*)d_in[17];
    const float* Wc3  = (const float*)d_in[18];
    const float* bc3  = (const float*)d_in[19];
    const float* Wf   = (const float*)d_in[20];
    const float* bf   = (const float*)d_in[21];
    const float* gf   = (const float*)d_in[22];
    const float* bef  = (const float*)d_in[23];
    const float* Wo   = (const float*)d_in[24];
    const float* bo   = (const float*)d_in[25];
    float* out = (float*)d_out;

    k_lin1 <<<64, 256>>>(x_sample, W1, b1, gl, bl);
    k_deg  <<<dim3(64, 2), 384>>>(x_graph);
    k_gsum <<<dim3(64, 2), 384>>>(x_graph, Wg, bg, g1, be1);
    k_conv1<<<64, 256>>>(Wc1, bc1, gc1, bec1);
    k_conv2<<<dim3(64, 4, 2), 256>>>(Wc2, bc2, gc2, bec2);
    k_conv3<<<dim3(16, 8), 256>>>(Wc3);
    k_fc   <<<64, 128>>>(bc3, Wf, bf, gf, bef, Wo, bo, out);
}

// round 2
// speedup vs baseline: 1.7816x; 1.7816x over previous
#include <cuda_runtime.h>
#include <cuda_bf16.h>

// ---------------------------------------------------------------------------
// Model_2 : FC -> graph conv (threshold adjacency) -> conv1d x3 -> FC -> logsoftmax
// B=64, N=750, F=8, NF=250
// ---------------------------------------------------------------------------

#define INV_BN 0.9999950000374997f   // 1/sqrt(1 + 1e-5)
#define GN 750

// Scratch (device globals; no dynamic allocation allowed)
__device__ float g_xcat[64 * 1000];          // concat [s(250) | g(750)] per batch
__device__ float g_pool1[64 * 32 * 500];     // after conv1+bn+relu+pool
__device__ float g_pool2[64 * 64 * 250];     // after conv2+bn+relu+pool
__device__ float g_part3[128 * 64 * 128];    // conv3 K-split partials [ks][b][oc]

// ---- packed f32x2 helpers (sm_100+ : 2x fp32 FMA throughput) ----------------
__device__ __forceinline__ unsigned long long pk2(float lo, float hi) {
    unsigned long long r;
    asm("mov.b64 %0, {%1,%2};" : "=l"(r) : "f"(lo), "f"(hi));
    return r;
}
__device__ __forceinline__ unsigned long long fma2(unsigned long long a,
                                                   unsigned long long b,
                                                   unsigned long long c) {
    unsigned long long d;
    asm("fma.rn.f32x2 %0, %1, %2, %3;" : "=l"(d) : "l"(a), "l"(b), "l"(c));
    return d;
}
__device__ __forceinline__ float2 upk2(unsigned long long v) {
    float2 r;
    asm("mov.b64 {%0,%1}, %2;" : "=f"(r.x), "=f"(r.y) : "l"(v));
    return r;
}

// ---------------------------------------------------------------------------
// K1: s = relu((x_sample @ W1 + b1) * inv * gl + bl)  -> g_xcat[b][0:250]
// ---------------------------------------------------------------------------
__global__ void k_lin1(const float* __restrict__ xs, const float* __restrict__ W1,
                       const float* __restrict__ b1, const float* __restrict__ gl,
                       const float* __restrict__ bl) {
    int b = blockIdx.x;
    __shared__ float xrow[250];
    int t = threadIdx.x;
    if (t < 250) xrow[t] = xs[b * 250 + t];
    __syncthreads();
    if (t < 250) {
        float acc = 0.f;
        #pragma unroll 5
        for (int k = 0; k < 250; k++) acc = fmaf(xrow[k], W1[k * 250 + t], acc);
        float v = (acc + b1[t]) * (INV_BN * gl[t]) + bl[t];
        g_xcat[b * 1000 + t] = fmaxf(v, 0.f);
    }
}

// ---------------------------------------------------------------------------
// K2: graph conv via sort + exact interval search + prefix sums.
// (diff*diff < 0.01f) is monotone in |diff| in fp32, so for sorted d the
// adjacency set of node i is a contiguous index interval -> binary search
// with the IDENTICAL predicate reproduces the exact reference edge set.
// One block per batch, 768 threads.
// ---------------------------------------------------------------------------
__global__ void k_graph(const float* __restrict__ xg, const float* __restrict__ Wg,
                        const float* __restrict__ bg, const float* __restrict__ g1,
                        const float* __restrict__ be1) {
    int b = blockIdx.x, t = threadIdx.x;
    __shared__ float sd[1024];
    __shared__ int   si[1024];
    __shared__ float pre[751 * 8];
    __shared__ float wsum[24][8];
    __shared__ float wgs[64];

    for (int i = t; i < 1024; i += 768) {
        if (i < GN) { sd[i] = xg[b * 6000 + i * 8]; si[i] = i; }
        else        { sd[i] = __int_as_float(0x7f800000); si[i] = -1; }
    }
    if (t < 64) wgs[t] = Wg[t];
    __syncthreads();

    // bitonic sort ascending (keys sd, payload si)
    for (int k2 = 2; k2 <= 1024; k2 <<= 1) {
        for (int j = k2 >> 1; j > 0; j >>= 1) {
            for (int i = t; i < 1024; i += 768) {
                int ixj = i ^ j;
                if (ixj > i) {
                    float a = sd[i], c = sd[ixj];
                    bool up = ((i & k2) == 0);
                    if (up ? (a > c) : (a < c)) {
                        sd[i] = c; sd[ixj] = a;
                        int tmp = si[i]; si[i] = si[ixj]; si[ixj] = tmp;
                    }
                }
            }
            __syncthreads();
        }
    }

    // per sorted node: window [lo,hi) via exact binary search; y = x@Wg; v = dn*y
    float dn = 0.f;
    int lo = 0, hi = 0;
    float y[8];
    if (t < GN) {
        float dsv = sd[t];
        int L = 0, R = t;
        while (L < R) { int m = (L + R) >> 1; float df = dsv - sd[m];
                        if (df * df < 0.01f) R = m; else L = m + 1; }
        lo = L;
        L = t + 1; R = GN;
        while (L < R) { int m = (L + R) >> 1; float df = dsv - sd[m];
                        if (df * df < 0.01f) L = m + 1; else R = m; }
        hi = L;
        dn = rsqrtf((float)(hi - lo));
        int orig = si[t];
        const float4* xp = reinterpret_cast<const float4*>(xg + (size_t)b * 6000 + orig * 8);
        float4 a4 = xp[0], c4 = xp[1];
        float xv[8] = {a4.x, a4.y, a4.z, a4.w, c4.x, c4.y, c4.z, c4.w};
        #pragma unroll
        for (int f = 0; f < 8; f++) {
            float s = 0.f;
            #pragma unroll
            for (int fp = 0; fp < 8; fp++) s = fmaf(xv[fp], wgs[fp * 8 + f], s);
            y[f] = s * dn;
        }
    } else {
        #pragma unroll
        for (int f = 0; f < 8; f++) y[f] = 0.f;
    }

    // block-wide inclusive scan of v (8 features)
    int lane = t & 31, wrp = t >> 5;
    #pragma unroll
    for (int f = 0; f < 8; f++) {
        float v = y[f];
        #pragma unroll
        for (int d = 1; d < 32; d <<= 1) {
            float o = __shfl_up_sync(0xffffffffu, v, d);
            if (lane >= d) v += o;
        }
        y[f] = v;
    }
    if (lane == 31) {
        #pragma unroll
        for (int f = 0; f < 8; f++) wsum[wrp][f] = y[f];
    }
    __syncthreads();
    if (t < 8) {
        float run = 0.f;
        for (int w = 0; w < 24; w++) { float x = wsum[w][t]; wsum[w][t] = run; run += x; }
    }
    __syncthreads();
    if (t < GN) {
        #pragma unroll
        for (int f = 0; f < 8; f++) pre[(t + 1) * 8 + f] = y[f] + wsum[wrp][f];
    }
    if (t < 8) pre[t] = 0.f;
    __syncthreads();

    if (t < GN) {
        float sc = INV_BN * g1[0], sh = be1[0];
        float gsum = 0.f;
        #pragma unroll
        for (int f = 0; f < 8; f++) {
            float s = pre[hi * 8 + f] - pre[lo * 8 + f];
            float hv = fmaf(dn, s, bg[f]);
            hv = fmaf(hv, sc, sh);
            gsum += fmaxf(hv, 0.f);
        }
        g_xcat[b * 1000 + 250 + si[t]] = gsum * 0.125f;
    }
}

// ---------------------------------------------------------------------------
// K3: conv1 (1->32, k=5, pad=2) + bn + relu + maxpool2 : [64,1,1000] -> [64,32,500]
// grid (64, 4): pooled tile of 125
// ---------------------------------------------------------------------------
__global__ void k_conv1(const float* __restrict__ Wc1, const float* __restrict__ bc1,
                        const float* __restrict__ gc1, const float* __restrict__ bec1) {
    int b = blockIdx.x, pt = blockIdx.y;
    int p0 = pt * 125;
    __shared__ float xs2[256];     // slab m: q = 2*p0-2+m, m in [0,254)
    __shared__ float w[160], bb[32], gg[32], be[32];
    int t = threadIdx.x;
    for (int m = t; m < 254; m += 256) {
        int q = 2 * p0 - 2 + m;
        xs2[m] = (q >= 0 && q < 1000) ? g_xcat[b * 1000 + q] : 0.f;
    }
    if (t < 160) w[t] = Wc1[t];
    if (t < 32) { bb[t] = bc1[t]; gg[t] = gc1[t] * INV_BN; be[t] = bec1[t]; }
    __syncthreads();
    for (int idx = t; idx < 32 * 125; idx += 256) {
        int c = idx / 125, p = idx - c * 125;
        int m = 2 * p;   // window xs2[m .. m+5]
        float v0 = bb[c], v1 = bb[c];
        #pragma unroll
        for (int k = 0; k < 5; k++) {
            float wk = w[c * 5 + k];
            v0 = fmaf(xs2[m + k],     wk, v0);
            v1 = fmaf(xs2[m + 1 + k], wk, v1);
        }
        v0 = fmaf(v0, gg[c], be[c]);
        v1 = fmaf(v1, gg[c], be[c]);
        g_pool1[(b * 32 + c) * 500 + p0 + p] = fmaxf(fmaxf(v0, v1), 0.f);
    }
}

// ---------------------------------------------------------------------------
// K4: conv2 (32->64, k=5, pad=2) + bn + relu + maxpool2 : [64,32,500] -> [64,64,250]
// grid (b=64, ptile=4 (64 pooled), ochalf=2), 256 threads
// thread = 1 oc x 4 pooled p, packed f32x2 over the two conv positions
// ---------------------------------------------------------------------------
__global__ void k_conv2(const float* __restrict__ Wc2, const float* __restrict__ bc2,
                        const float* __restrict__ gc2, const float* __restrict__ bec2) {
    int b = blockIdx.x, pt = blockIdx.y, oh = blockIdx.z;
    int p0 = pt * 64;
    int oc0 = oh * 32;
    __shared__ __align__(16) float sx[32][132];  // slab m: q = 2*p0-2+m
    __shared__ float sw[32][160];
    __shared__ float bb[32], gg[32], be[32];
    int t = threadIdx.x;

    for (int i = t; i < 32 * 132; i += 256) {
        int ic = i / 132, m = i - ic * 132;
        int q = 2 * p0 - 2 + m;
        sx[ic][m] = (q >= 0 && q < 500) ? g_pool1[(b * 32 + ic) * 500 + q] : 0.f;
    }
    for (int i = t; i < 32 * 160; i += 256) {
        int o = i / 160, j = i - o * 160;
        sw[o][j] = Wc2[(oc0 + o) * 160 + j];
    }
    if (t < 32) { bb[t] = bc2[oc0 + t]; gg[t] = gc2[oc0 + t] * INV_BN; be[t] = bec2[oc0 + t]; }
    __syncthreads();

    int tq  = t & 15;      // p-quad: local pooled pl = 4*tq .. 4*tq+3
    int ocb = t >> 4;      // 0..15
    int m0  = 8 * tq;      // slab start (16B aligned: 32B multiple)

    #pragma unroll 1
    for (int iter = 0; iter < 2; iter++) {
        int oc = ocb + 16 * iter;
        unsigned long long acc0, acc1, acc2, acc3;
        { unsigned long long bi = pk2(bb[oc], bb[oc]); acc0 = bi; acc1 = bi; acc2 = bi; acc3 = bi; }
        const float* wrow = sw[oc];
        #pragma unroll 4
        for (int ic = 0; ic < 32; ic++) {
            const float4* xr = reinterpret_cast<const float4*>(&sx[ic][m0]);
            float4 xa = xr[0], xb = xr[1], xc = xr[2];
            float lx[12] = {xa.x, xa.y, xa.z, xa.w, xb.x, xb.y, xb.z, xb.w,
                            xc.x, xc.y, xc.z, xc.w};
            unsigned long long xp[11];
            #pragma unroll
            for (int j = 0; j < 11; j++) xp[j] = pk2(lx[j], lx[j + 1]);
            #pragma unroll
            for (int k = 0; k < 5; k++) {
                float wv = wrow[ic * 5 + k];
                unsigned long long wd = pk2(wv, wv);
                acc0 = fma2(xp[0 + k], wd, acc0);
                acc1 = fma2(xp[2 + k], wd, acc1);
                acc2 = fma2(xp[4 + k], wd, acc2);
                acc3 = fma2(xp[6 + k], wd, acc3);
            }
        }
        unsigned long long accs[4] = {acc0, acc1, acc2, acc3};
        #pragma unroll
        for (int i2 = 0; i2 < 4; i2++) {
            float2 v = upk2(accs[i2]);
            float r0 = fmaf(v.x, gg[oc], be[oc]);
            float r1 = fmaf(v.y, gg[oc], be[oc]);
            int p = p0 + 4 * tq + i2;
            if (p < 250)
                g_pool2[(b * 64 + oc0 + oc) * 250 + p] = fmaxf(fmaxf(r0, r1), 0.f);
        }
    }
}

// ---------------------------------------------------------------------------
// K5: conv3 as K-split GEMM: part[ks][b][oc] = sum_{k in split} X[b][k]*W[oc][k]
// grid 128 (K-splits of 125), 256 threads; thread = 4b x 8oc, f32x2 over b-pairs
// ---------------------------------------------------------------------------
__global__ void k_conv3(const float* __restrict__ Wc3) {
    int ks = blockIdx.x;       // 0..127
    int t = threadIdx.x;
    __shared__ __align__(16) float Xs[25][72];
    __shared__ float Ws[128][26];
    int bq = t & 15;           // b0 = 4*bq
    int og = t >> 4;           // oc group: oc = 8*og + o
    unsigned long long acc[8][2];
    #pragma unroll
    for (int o = 0; o < 8; o++) { acc[o][0] = pk2(0.f, 0.f); acc[o][1] = pk2(0.f, 0.f); }
    int kbase = ks * 125;
    for (int c = 0; c < 5; c++) {
        int k0 = kbase + c * 25;
        __syncthreads();
        for (int i = t; i < 1600; i += 256) {
            int bb2 = i / 25, kk = i - bb2 * 25;
            Xs[kk][bb2] = g_pool2[bb2 * 16000 + k0 + kk];
        }
        for (int i = t; i < 3200; i += 256) {
            int o = i / 25, kk = i - o * 25;
            Ws[o][kk] = Wc3[o * 16000 + k0 + kk];
        }
        __syncthreads();
        #pragma unroll 5
        for (int kk = 0; kk < 25; kk++) {
            const float4* xr = reinterpret_cast<const float4*>(&Xs[kk][4 * bq]);
            float4 xv = xr[0];
            unsigned long long xp0 = pk2(xv.x, xv.y), xp1 = pk2(xv.z, xv.w);
            #pragma unroll
            for (int o = 0; o < 8; o++) {
                float wv = Ws[og * 8 + o][kk];
                unsigned long long wd = pk2(wv, wv);
                acc[o][0] = fma2(xp0, wd, acc[o][0]);
                acc[o][1] = fma2(xp1, wd, acc[o][1]);
            }
        }
    }
    #pragma unroll
    for (int o = 0; o < 8; o++) {
        float2 v0 = upk2(acc[o][0]), v1 = upk2(acc[o][1]);
        int oc = og * 8 + o, b0 = 4 * bq;
        g_part3[(ks * 64 + b0 + 0) * 128 + oc] = v0.x;
        g_part3[(ks * 64 + b0 + 1) * 128 + oc] = v0.y;
        g_part3[(ks * 64 + b0 + 2) * 128 + oc] = v1.x;
        g_part3[(ks * 64 + b0 + 3) * 128 + oc] = v1.y;
    }
}

// ---------------------------------------------------------------------------
// K6: reduce partials (+bc3), FC 128->64 (+bn relu), FC 64->12, log_softmax
// one block per batch, 128 threads
// ---------------------------------------------------------------------------
__global__ void k_fc(const float* __restrict__ bc3, const float* __restrict__ Wf,
                     const float* __restrict__ bf, const float* __restrict__ gf,
                     const float* __restrict__ bef, const float* __restrict__ Wo,
                     const float* __restrict__ bo, float* __restrict__ out) {
    int b = blockIdx.x;
    int t = threadIdx.x;
    __shared__ float f[128], u[64], o[12];
    {
        float s0 = 0.f, s1 = 0.f, s2 = 0.f, s3 = 0.f;
        #pragma unroll 4
        for (int ks = 0; ks < 128; ks += 4) {
            s0 += g_part3[((ks + 0) * 64 + b) * 128 + t];
            s1 += g_part3[((ks + 1) * 64 + b) * 128 + t];
            s2 += g_part3[((ks + 2) * 64 + b) * 128 + t];
            s3 += g_part3[((ks + 3) * 64 + b) * 128 + t];
        }
        f[t] = bc3[t] + ((s0 + s1) + (s2 + s3));
    }
    __syncthreads();
    if (t < 64) {
        float z = bf[t];
        #pragma unroll 8
        for (int k = 0; k < 128; k++) z = fmaf(f[k], Wf[k * 64 + t], z);
        z = z * (INV_BN * gf[t]) + bef[t];
        u[t] = fmaxf(z, 0.f);
    }
    __syncthreads();
    if (t < 12) {
        float z = bo[t];
        #pragma unroll 8
        for (int k = 0; k < 64; k++) z = fmaf(u[k], Wo[k * 12 + t], z);
        o[t] = z;
    }
    __syncthreads();
    if (t < 12) {
        float m = o[0];
        #pragma unroll
        for (int i = 1; i < 12; i++) m = fmaxf(m, o[i]);
        float s = 0.f;
        #pragma unroll
        for (int i = 0; i < 12; i++) s += expf(o[i] - m);
        out[b * 12 + t] = (o[t] - m) - logf(s);
    }
}

// ---------------------------------------------------------------------------
extern "C" void kernel_launch(void* const* d_in, const int* in_sizes, int n_in,
                              void* d_out, int out_size) {
    const float* x_sample = (const float*)d_in[0];
    const float* x_graph  = (const float*)d_in[1];
    const float* W1   = (const float*)d_in[2];
    const float* b1   = (const float*)d_in[3];
    const float* gl   = (const float*)d_in[4];
    const float* bl   = (const float*)d_in[5];
    const float* Wg   = (const float*)d_in[6];
    const float* bg   = (const float*)d_in[7];
    const float* g1   = (const float*)d_in[8];
    const float* be1  = (const float*)d_in[9];
    const float* Wc1  = (const float*)d_in[10];
    const float* bc1  = (const float*)d_in[11];
    const float* gc1  = (const float*)d_in[12];
    const float* bec1 = (const float*)d_in[13];
    const float* Wc2  = (const float*)d_in[14];
    const float* bc2  = (const float*)d_in[15];
    const float* gc2  = (const float*)d_in[16];
    const float* bec2 = (const float*)d_in[17];
    const float* Wc3  = (const float*)d_in[18];
    const float* bc3  = (const float*)d_in[19];
    const float* Wf   = (const float*)d_in[20];
    const float* bf   = (const float*)d_in[21];
    const float* gf   = (const float*)d_in[22];
    const float* bef  = (const float*)d_in[23];
    const float* Wo   = (const float*)d_in[24];
    const float* bo   = (const float*)d_in[25];
    float* out = (float*)d_out;

    k_lin1 <<<64, 256>>>(x_sample, W1, b1, gl, bl);
    k_graph<<<64, 768>>>(x_graph, Wg, bg, g1, be1);
    k_conv1<<<dim3(64, 4), 256>>>(Wc1, bc1, gc1, bec1);
    k_conv2<<<dim3(64, 4, 2), 256>>>(Wc2, bc2, gc2, bec2);
    k_conv3<<<128, 256>>>(Wc3);
    k_fc   <<<64, 128>>>(bc3, Wf, bf, gf, bef, Wo, bo, out);
}

// round 3
// speedup vs baseline: 1.9338x; 1.0855x over previous
#include <cuda_runtime.h>
#include <cuda_bf16.h>

// ---------------------------------------------------------------------------
// Model_2 : FC -> graph conv (threshold adjacency) -> conv1d x3 -> FC -> logsoftmax
// B=64, N=750, F=8, NF=250
// ---------------------------------------------------------------------------

#define INV_BN 0.9999950000374997f   // 1/sqrt(1 + 1e-5)
#define GN 750

typedef unsigned long long ull;

// Scratch (device globals; no dynamic allocation allowed)
__device__ float g_xcat[64 * 1000];          // concat [s(250) | g(750)] per batch
__device__ float g_pool1[64 * 32 * 500];     // after conv1+bn+relu+pool
__device__ float g_pool2[64 * 64 * 250];     // after conv2+bn+relu+pool
__device__ float g_part3[250 * 64 * 128];    // conv3 K-split partials [ks][b][oc]

// ---- packed f32x2 helpers (sm_100+ : 2x fp32 FMA throughput) ----------------
__device__ __forceinline__ ull pk2(float lo, float hi) {
    ull r;
    asm("mov.b64 %0, {%1,%2};" : "=l"(r) : "f"(lo), "f"(hi));
    return r;
}
__device__ __forceinline__ ull fma2(ull a, ull b, ull c) {
    ull d;
    asm("fma.rn.f32x2 %0, %1, %2, %3;" : "=l"(d) : "l"(a), "l"(b), "l"(c));
    return d;
}
__device__ __forceinline__ float2 upk2(ull v) {
    float2 r;
    asm("mov.b64 {%0,%1}, %2;" : "=f"(r.x), "=f"(r.y) : "l"(v));
    return r;
}

// ---------------------------------------------------------------------------
// K1: s = relu((x_sample @ W1 + b1) * inv * gl + bl)  -> g_xcat[b][0:250]
// ---------------------------------------------------------------------------
__global__ void k_lin1(const float* __restrict__ xs, const float* __restrict__ W1,
                       const float* __restrict__ b1, const float* __restrict__ gl,
                       const float* __restrict__ bl) {
    int b = blockIdx.x;
    __shared__ float xrow[250];
    int t = threadIdx.x;
    if (t < 250) xrow[t] = xs[b * 250 + t];
    __syncthreads();
    if (t < 250) {
        float acc = 0.f;
        #pragma unroll 5
        for (int k = 0; k < 250; k++) acc = fmaf(xrow[k], W1[k * 250 + t], acc);
        float v = (acc + b1[t]) * (INV_BN * gl[t]) + bl[t];
        g_xcat[b * 1000 + t] = fmaxf(v, 0.f);
    }
}

// ---------------------------------------------------------------------------
// K2: graph conv via sort + exact interval search + prefix sums.
// (diff*diff < 0.01f) is monotone in |diff| in fp32 -> adjacency = contiguous
// interval in sorted order; binary search with the IDENTICAL predicate
// reproduces the exact reference edge set. One block per batch, 768 threads.
// ---------------------------------------------------------------------------
__global__ void k_graph(const float* __restrict__ xg, const float* __restrict__ Wg,
                        const float* __restrict__ bg, const float* __restrict__ g1,
                        const float* __restrict__ be1) {
    int b = blockIdx.x, t = threadIdx.x;
    __shared__ float sd[1024];
    __shared__ int   si[1024];
    __shared__ float pre[751 * 8];
    __shared__ float wsum[24][8];
    __shared__ float wgs[64];

    for (int i = t; i < 1024; i += 768) {
        if (i < GN) { sd[i] = xg[b * 6000 + i * 8]; si[i] = i; }
        else        { sd[i] = __int_as_float(0x7f800000); si[i] = -1; }
    }
    if (t < 64) wgs[t] = Wg[t];
    __syncthreads();

    // bitonic sort ascending (keys sd, payload si)
    for (int k2 = 2; k2 <= 1024; k2 <<= 1) {
        for (int j = k2 >> 1; j > 0; j >>= 1) {
            for (int i = t; i < 1024; i += 768) {
                int ixj = i ^ j;
                if (ixj > i) {
                    float a = sd[i], c = sd[ixj];
                    bool up = ((i & k2) == 0);
                    if (up ? (a > c) : (a < c)) {
                        sd[i] = c; sd[ixj] = a;
                        int tmp = si[i]; si[i] = si[ixj]; si[ixj] = tmp;
                    }
                }
            }
            __syncthreads();
        }
    }

    float dn = 0.f;
    int lo = 0, hi = 0;
    float y[8];
    if (t < GN) {
        float dsv = sd[t];
        int L = 0, R = t;
        while (L < R) { int m = (L + R) >> 1; float df = dsv - sd[m];
                        if (df * df < 0.01f) R = m; else L = m + 1; }
        lo = L;
        L = t + 1; R = GN;
        while (L < R) { int m = (L + R) >> 1; float df = dsv - sd[m];
                        if (df * df < 0.01f) L = m + 1; else R = m; }
        hi = L;
        dn = rsqrtf((float)(hi - lo));
        int orig = si[t];
        const float4* xp = reinterpret_cast<const float4*>(xg + (size_t)b * 6000 + orig * 8);
        float4 a4 = xp[0], c4 = xp[1];
        float xv[8] = {a4.x, a4.y, a4.z, a4.w, c4.x, c4.y, c4.z, c4.w};
        #pragma unroll
        for (int f = 0; f < 8; f++) {
            float s = 0.f;
            #pragma unroll
            for (int fp = 0; fp < 8; fp++) s = fmaf(xv[fp], wgs[fp * 8 + f], s);
            y[f] = s * dn;
        }
    } else {
        #pragma unroll
        for (int f = 0; f < 8; f++) y[f] = 0.f;
    }

    int lane = t & 31, wrp = t >> 5;
    #pragma unroll
    for (int f = 0; f < 8; f++) {
        float v = y[f];
        #pragma unroll
        for (int d = 1; d < 32; d <<= 1) {
            float o = __shfl_up_sync(0xffffffffu, v, d);
            if (lane >= d) v += o;
        }
        y[f] = v;
    }
    if (lane == 31) {
        #pragma unroll
        for (int f = 0; f < 8; f++) wsum[wrp][f] = y[f];
    }
    __syncthreads();
    if (t < 8) {
        float run = 0.f;
        for (int w = 0; w < 24; w++) { float x = wsum[w][t]; wsum[w][t] = run; run += x; }
    }
    __syncthreads();
    if (t < GN) {
        #pragma unroll
        for (int f = 0; f < 8; f++) pre[(t + 1) * 8 + f] = y[f] + wsum[wrp][f];
    }
    if (t < 8) pre[t] = 0.f;
    __syncthreads();

    if (t < GN) {
        float sc = INV_BN * g1[0], sh = be1[0];
        float gsum = 0.f;
        #pragma unroll
        for (int f = 0; f < 8; f++) {
            float s = pre[hi * 8 + f] - pre[lo * 8 + f];
            float hv = fmaf(dn, s, bg[f]);
            hv = fmaf(hv, sc, sh);
            gsum += fmaxf(hv, 0.f);
        }
        g_xcat[b * 1000 + 250 + si[t]] = gsum * 0.125f;
    }
}

// ---------------------------------------------------------------------------
// K3: conv1 (1->32, k=5, pad=2) + bn + relu + maxpool2 : [64,1,1000] -> [64,32,500]
// grid (64, 4): pooled tile of 125
// ---------------------------------------------------------------------------
__global__ void k_conv1(const float* __restrict__ Wc1, const float* __restrict__ bc1,
                        const float* __restrict__ gc1, const float* __restrict__ bec1) {
    int b = blockIdx.x, pt = blockIdx.y;
    int p0 = pt * 125;
    __shared__ float xs2[256];
    __shared__ float w[160], bb[32], gg[32], be[32];
    int t = threadIdx.x;
    for (int m = t; m < 254; m += 256) {
        int q = 2 * p0 - 2 + m;
        xs2[m] = (q >= 0 && q < 1000) ? g_xcat[b * 1000 + q] : 0.f;
    }
    if (t < 160) w[t] = Wc1[t];
    if (t < 32) { bb[t] = bc1[t]; gg[t] = gc1[t] * INV_BN; be[t] = bec1[t]; }
    __syncthreads();
    for (int idx = t; idx < 32 * 125; idx += 256) {
        int c = idx / 125, p = idx - c * 125;
        int m = 2 * p;
        float v0 = bb[c], v1 = bb[c];
        #pragma unroll
        for (int k = 0; k < 5; k++) {
            float wk = w[c * 5 + k];
            v0 = fmaf(xs2[m + k],     wk, v0);
            v1 = fmaf(xs2[m + 1 + k], wk, v1);
        }
        v0 = fmaf(v0, gg[c], be[c]);
        v1 = fmaf(v1, gg[c], be[c]);
        g_pool1[(b * 32 + c) * 500 + p0 + p] = fmaxf(fmaxf(v0, v1), 0.f);
    }
}

// ---------------------------------------------------------------------------
// K4: conv2 (32->64, k=5, pad=2) + bn + relu + maxpool2 : [64,32,500] -> [64,64,250]
// grid (b=64, ptile=8 (32 pooled), ochalf=2), 256 threads.
// Thread = oc-PAIR (packed in f32x2 lanes) x 4 conv positions (2 pooled).
// x stored PRE-DUPLICATED (v,v) as float2 -> packed operand via LDS.128 only.
// weights stored as (w[oc0],w[oc1]) float2 pairs -> one LDS.64 per (ic,k).
// ---------------------------------------------------------------------------
__global__ void __launch_bounds__(256) k_conv2(
        const float* __restrict__ Wc2, const float* __restrict__ bc2,
        const float* __restrict__ gc2, const float* __restrict__ bec2) {
    int b = blockIdx.x, pt = blockIdx.y, oh = blockIdx.z;
    int p0 = pt * 32;            // pooled start; conv start = 2*p0
    int oc0 = oh * 32;
    __shared__ __align__(16) float2 sxd[32][68];      // (v,v) duplicated, m: q=2*p0-2+m
    __shared__ __align__(16) float2 sw2[32][5][16];   // (w[oc0+2op], w[oc0+2op+1])
    __shared__ float2 sb2[16], sg2[16], se2[16];
    int t = threadIdx.x;

    for (int i = t; i < 32 * 68; i += 256) {
        int ic = i / 68, m = i - ic * 68;
        int q = 2 * p0 - 2 + m;
        float v = (q >= 0 && q < 500) ? g_pool1[(b * 32 + ic) * 500 + q] : 0.f;
        sxd[ic][m] = make_float2(v, v);
    }
    for (int i = t; i < 2560; i += 256) {
        int ic = i / 80, r = i - ic * 80;
        int k = r / 16, op = r - k * 16;
        const float* wp = Wc2 + (oc0 + 2 * op) * 160 + ic * 5 + k;
        sw2[ic][k][op] = make_float2(wp[0], wp[160]);
    }
    if (t < 16) {
        sb2[t] = make_float2(bc2[oc0 + 2 * t], bc2[oc0 + 2 * t + 1]);
        sg2[t] = make_float2(gc2[oc0 + 2 * t] * INV_BN, gc2[oc0 + 2 * t + 1] * INV_BN);
        se2[t] = make_float2(bec2[oc0 + 2 * t], bec2[oc0 + 2 * t + 1]);
    }
    __syncthreads();

    int op = t & 15;         // oc pair index (16 lanes: conflict-free 128B LDS.64 row)
    int pg = t >> 4;         // 0..15 -> conv positions 4pg..4pg+3 (broadcast x loads)

    float2 bp = sb2[op];
    ull bini = pk2(bp.x, bp.y);
    ull acc0 = bini, acc1 = bini, acc2 = bini, acc3 = bini;

    #pragma unroll 4
    for (int ic = 0; ic < 32; ic++) {
        const ulonglong2* xr = reinterpret_cast<const ulonglong2*>(&sxd[ic][4 * pg]);
        ulonglong2 q0 = xr[0], q1 = xr[1], q2 = xr[2], q3 = xr[3];
        ull xd0 = q0.x, xd1 = q0.y, xd2 = q1.x, xd3 = q1.y;
        ull xd4 = q2.x, xd5 = q2.y, xd6 = q3.x, xd7 = q3.y;
        ull w;
        w = *reinterpret_cast<const ull*>(&sw2[ic][0][op]);
        acc0 = fma2(xd0, w, acc0); acc1 = fma2(xd1, w, acc1);
        acc2 = fma2(xd2, w, acc2); acc3 = fma2(xd3, w, acc3);
        w = *reinterpret_cast<const ull*>(&sw2[ic][1][op]);
        acc0 = fma2(xd1, w, acc0); acc1 = fma2(xd2, w, acc1);
        acc2 = fma2(xd3, w, acc2); acc3 = fma2(xd4, w, acc3);
        w = *reinterpret_cast<const ull*>(&sw2[ic][2][op]);
        acc0 = fma2(xd2, w, acc0); acc1 = fma2(xd3, w, acc1);
        acc2 = fma2(xd4, w, acc2); acc3 = fma2(xd5, w, acc3);
        w = *reinterpret_cast<const ull*>(&sw2[ic][3][op]);
        acc0 = fma2(xd3, w, acc0); acc1 = fma2(xd4, w, acc1);
        acc2 = fma2(xd5, w, acc2); acc3 = fma2(xd6, w, acc3);
        w = *reinterpret_cast<const ull*>(&sw2[ic][4][op]);
        acc0 = fma2(xd4, w, acc0); acc1 = fma2(xd5, w, acc1);
        acc2 = fma2(xd6, w, acc2); acc3 = fma2(xd7, w, acc3);
    }

    float2 gp = sg2[op], ep = se2[op];
    float2 a0 = upk2(acc0), a1 = upk2(acc1), a2 = upk2(acc2), a3 = upk2(acc3);
    int base0 = (b * 64 + oc0 + 2 * op) * 250;
    int base1 = base0 + 250;
    int p = p0 + 2 * pg;
    if (p < 250) {
        float r0 = fmaxf(fmaxf(fmaf(a0.x, gp.x, ep.x), fmaf(a1.x, gp.x, ep.x)), 0.f);
        float r1 = fmaxf(fmaxf(fmaf(a0.y, gp.y, ep.y), fmaf(a1.y, gp.y, ep.y)), 0.f);
        g_pool2[base0 + p] = r0;
        g_pool2[base1 + p] = r1;
    }
    if (p + 1 < 250) {
        float r0 = fmaxf(fmaxf(fmaf(a2.x, gp.x, ep.x), fmaf(a3.x, gp.x, ep.x)), 0.f);
        float r1 = fmaxf(fmaxf(fmaf(a2.y, gp.y, ep.y), fmaf(a3.y, gp.y, ep.y)), 0.f);
        g_pool2[base0 + p + 1] = r0;
        g_pool2[base1 + p + 1] = r1;
    }
}

// ---------------------------------------------------------------------------
// K5: conv3 K-split GEMM: part[ks][b][oc] = sum_{k in 64-chunk} X[b][k]*W[oc][k]
// grid 250 K-splits, 256 threads; thread = 4 oc-pairs (8 oc) x 4 b.
// x duplicated (v,v) in shared; weights as (w[2op],w[2op+1]) pairs in shared.
// ---------------------------------------------------------------------------
__global__ void __launch_bounds__(256) k_conv3(const float* __restrict__ Wc3) {
    int ks = blockIdx.x;       // 0..249
    int t = threadIdx.x;
    __shared__ __align__(16) float2 Xsd[32][64];   // [kk][b] duplicated
    __shared__ __align__(16) float2 Ws2[32][64];   // [kk][op] oc-pairs
    int og = t & 15;           // op = 4og+o -> oc = 8og+2o {,+1}
    int bg = t >> 4;           // b = 4bg + j
    ull acc[4][4];
    #pragma unroll
    for (int o = 0; o < 4; o++)
        #pragma unroll
        for (int j = 0; j < 4; j++) acc[o][j] = 0ull;

    int kbase = ks * 64;
    #pragma unroll 1
    for (int c = 0; c < 2; c++) {
        int k0 = kbase + c * 32;
        __syncthreads();
        for (int i = t; i < 2048; i += 256) {
            int bb2 = i >> 5, kk = i & 31;
            float v = g_pool2[bb2 * 16000 + k0 + kk];
            Xsd[kk][bb2] = make_float2(v, v);
        }
        for (int i = t; i < 2048; i += 256) {
            int opi = i >> 5, kk = i & 31;
            const float* wp = Wc3 + (2 * opi) * 16000 + k0 + kk;
            Ws2[kk][opi] = make_float2(wp[0], wp[16000]);
        }
        __syncthreads();
        #pragma unroll 4
        for (int kk = 0; kk < 32; kk++) {
            const ulonglong2* xr = reinterpret_cast<const ulonglong2*>(&Xsd[kk][4 * bg]);
            ulonglong2 xq0 = xr[0], xq1 = xr[1];
            ull xd0 = xq0.x, xd1 = xq0.y, xd2 = xq1.x, xd3 = xq1.y;
            const ulonglong2* wr = reinterpret_cast<const ulonglong2*>(&Ws2[kk][4 * og]);
            ulonglong2 wq0 = wr[0], wq1 = wr[1];
            ull wd0 = wq0.x, wd1 = wq0.y, wd2 = wq1.x, wd3 = wq1.y;
            acc[0][0] = fma2(xd0, wd0, acc[0][0]); acc[0][1] = fma2(xd1, wd0, acc[0][1]);
            acc[0][2] = fma2(xd2, wd0, acc[0][2]); acc[0][3] = fma2(xd3, wd0, acc[0][3]);
            acc[1][0] = fma2(xd0, wd1, acc[1][0]); acc[1][1] = fma2(xd1, wd1, acc[1][1]);
            acc[1][2] = fma2(xd2, wd1, acc[1][2]); acc[1][3] = fma2(xd3, wd1, acc[1][3]);
            acc[2][0] = fma2(xd0, wd2, acc[2][0]); acc[2][1] = fma2(xd1, wd2, acc[2][1]);
            acc[2][2] = fma2(xd2, wd2, acc[2][2]); acc[2][3] = fma2(xd3, wd2, acc[2][3]);
            acc[3][0] = fma2(xd0, wd3, acc[3][0]); acc[3][1] = fma2(xd1, wd3, acc[3][1]);
            acc[3][2] = fma2(xd2, wd3, acc[3][2]); acc[3][3] = fma2(xd3, wd3, acc[3][3]);
        }
    }
    #pragma unroll
    for (int o = 0; o < 4; o++) {
        int oc = 8 * og + 2 * o;
        #pragma unroll
        for (int j = 0; j < 4; j++) {
            float2 v = upk2(acc[o][j]);
            int bb2 = 4 * bg + j;
            *reinterpret_cast<float2*>(&g_part3[(ks * 64 + bb2) * 128 + oc]) = v;
        }
    }
}

// ---------------------------------------------------------------------------
// K6: reduce partials (+bc3), FC 128->64 (+bn relu), FC 64->12, log_softmax
// one block per batch, 128 threads
// ---------------------------------------------------------------------------
__global__ void k_fc(const float* __restrict__ bc3, const float* __restrict__ Wf,
                     const float* __restrict__ bf, const float* __restrict__ gf,
                     const float* __restrict__ bef, const float* __restrict__ Wo,
                     const float* __restrict__ bo, float* __restrict__ out) {
    int b = blockIdx.x;
    int t = threadIdx.x;
    __shared__ float f[128], u[64], o[12];
    {
        float s0 = 0.f, s1 = 0.f;
        #pragma unroll 5
        for (int ks = 0; ks < 250; ks += 2) {
            s0 += g_part3[((ks + 0) * 64 + b) * 128 + t];
            s1 += g_part3[((ks + 1) * 64 + b) * 128 + t];
        }
        f[t] = bc3[t] + (s0 + s1);
    }
    __syncthreads();
    if (t < 64) {
        float z = bf[t];
        #pragma unroll 8
        for (int k = 0; k < 128; k++) z = fmaf(f[k], Wf[k * 64 + t], z);
        z = z * (INV_BN * gf[t]) + bef[t];
        u[t] = fmaxf(z, 0.f);
    }
    __syncthreads();
    if (t < 12) {
        float z = bo[t];
        #pragma unroll 8
        for (int k = 0; k < 64; k++) z = fmaf(u[k], Wo[k * 12 + t], z);
        o[t] = z;
    }
    __syncthreads();
    if (t < 12) {
        float m = o[0];
        #pragma unroll
        for (int i = 1; i < 12; i++) m = fmaxf(m, o[i]);
        float s = 0.f;
        #pragma unroll
        for (int i = 0; i < 12; i++) s += expf(o[i] - m);
        out[b * 12 + t] = (o[t] - m) - logf(s);
    }
}

// ---------------------------------------------------------------------------
extern "C" void kernel_launch(void* const* d_in, const int* in_sizes, int n_in,
                              void* d_out, int out_size) {
    const float* x_sample = (const float*)d_in[0];
    const float* x_graph  = (const float*)d_in[1];
    const float* W1   = (const float*)d_in[2];
    const float* b1   = (const float*)d_in[3];
    const float* gl   = (const float*)d_in[4];
    const float* bl   = (const float*)d_in[5];
    const float* Wg   = (const float*)d_in[6];
    const float* bg   = (const float*)d_in[7];
    const float* g1   = (const float*)d_in[8];
    const float* be1  = (const float*)d_in[9];
    const float* Wc1  = (const float*)d_in[10];
    const float* bc1  = (const float*)d_in[11];
    const float* gc1  = (const float*)d_in[12];
    const float* bec1 = (const float*)d_in[13];
    const float* Wc2  = (const float*)d_in[14];
    const float* bc2  = (const float*)d_in[15];
    const float* gc2  = (const float*)d_in[16];
    const float* bec2 = (const float*)d_in[17];
    const float* Wc3  = (const float*)d_in[18];
    const float* bc3  = (const float*)d_in[19];
    const float* Wf   = (const float*)d_in[20];
    const float* bf   = (const float*)d_in[21];
    const float* gf   = (const float*)d_in[22];
    const float* bef  = (const float*)d_in[23];
    const float* Wo   = (const float*)d_in[24];
    const float* bo   = (const float*)d_in[25];
    float* out = (float*)d_out;

    k_lin1 <<<64, 256>>>(x_sample, W1, b1, gl, bl);
    k_graph<<<64, 768>>>(x_graph, Wg, bg, g1, be1);
    k_conv1<<<dim3(64, 4), 256>>>(Wc1, bc1, gc1, bec1);
    k_conv2<<<dim3(64, 8, 2), 256>>>(Wc2, bc2, gc2, bec2);
    k_conv3<<<250, 256>>>(Wc3);
    k_fc   <<<64, 128>>>(bc3, Wf, bf, gf, bef, Wo, bo, out);
}

// round 4
// speedup vs baseline: 2.5644x; 1.3261x over previous
#include <cuda_runtime.h>
#include <cuda_bf16.h>

// ---------------------------------------------------------------------------
// Model_2 : FC -> graph conv (threshold adjacency) -> conv1d x3 -> FC -> logsoftmax
// B=64, N=750, F=8, NF=250
// ---------------------------------------------------------------------------

#define INV_BN 0.9999950000374997f   // 1/sqrt(1 + 1e-5)
#define GN 750

typedef unsigned long long ull;

// Scratch (device globals; no dynamic allocation allowed)
__device__ float g_xcat[64 * 1000];          // concat [s(250) | g(750)] per batch
__device__ float g_pool1[64 * 32 * 500];     // after conv1+bn+relu+pool
__device__ float g_pool2[64 * 64 * 250];     // after conv2+bn+relu+pool
__device__ float g_part3[250 * 64 * 128];    // conv3 K-split partials [ks][b][oc]

// ---- packed f32x2 helpers (sm_100+ : 2x fp32 FMA throughput) ----------------
__device__ __forceinline__ ull pk2(float lo, float hi) {
    ull r;
    asm("mov.b64 %0, {%1,%2};" : "=l"(r) : "f"(lo), "f"(hi));
    return r;
}
__device__ __forceinline__ ull fma2(ull a, ull b, ull c) {
    ull d;
    asm("fma.rn.f32x2 %0, %1, %2, %3;" : "=l"(d) : "l"(a), "l"(b), "l"(c));
    return d;
}
__device__ __forceinline__ float2 upk2(ull v) {
    float2 r;
    asm("mov.b64 {%0,%1}, %2;" : "=f"(r.x), "=f"(r.y) : "l"(v));
    return r;
}

// ---------------------------------------------------------------------------
// K_front: blocks 0..63 -> graph conv per batch; blocks 64..127 -> linear1.
// Graph: sort + exact interval search + prefix sums. (diff*diff < 0.01f) is
// monotone in |diff| in fp32 -> adjacency = contiguous interval in sorted
// order; binary search with the IDENTICAL predicate reproduces the exact
// reference edge set.
// ---------------------------------------------------------------------------
__global__ void __launch_bounds__(768) k_front(
        const float* __restrict__ xs, const float* __restrict__ W1,
        const float* __restrict__ b1, const float* __restrict__ gl,
        const float* __restrict__ bl,
        const float* __restrict__ xg, const float* __restrict__ Wg,
        const float* __restrict__ bg, const float* __restrict__ g1,
        const float* __restrict__ be1) {
    int t = threadIdx.x;
    __shared__ float sd[1024];
    __shared__ int   si[1024];
    __shared__ float pre[751 * 8];
    __shared__ float wsum[24][8];
    __shared__ float wgs[64];

    if (blockIdx.x >= 64) {
        // ------- linear1 path -------
        int b = blockIdx.x - 64;
        if (t < 250) sd[t] = xs[b * 250 + t];
        __syncthreads();
        if (t < 250) {
            float acc = 0.f;
            #pragma unroll 5
            for (int k = 0; k < 250; k++) acc = fmaf(sd[k], W1[k * 250 + t], acc);
            float v = (acc + b1[t]) * (INV_BN * gl[t]) + bl[t];
            g_xcat[b * 1000 + t] = fmaxf(v, 0.f);
        }
        return;
    }

    // ------- graph path -------
    int b = blockIdx.x;
    for (int i = t; i < 1024; i += 768) {
        if (i < GN) { sd[i] = xg[b * 6000 + i * 8]; si[i] = i; }
        else        { sd[i] = __int_as_float(0x7f800000); si[i] = -1; }
    }
    if (t < 64) wgs[t] = Wg[t];
    __syncthreads();

    // bitonic sort ascending (keys sd, payload si)
    for (int k2 = 2; k2 <= 1024; k2 <<= 1) {
        for (int j = k2 >> 1; j > 0; j >>= 1) {
            for (int i = t; i < 1024; i += 768) {
                int ixj = i ^ j;
                if (ixj > i) {
                    float a = sd[i], c = sd[ixj];
                    bool up = ((i & k2) == 0);
                    if (up ? (a > c) : (a < c)) {
                        sd[i] = c; sd[ixj] = a;
                        int tmp = si[i]; si[i] = si[ixj]; si[ixj] = tmp;
                    }
                }
            }
            __syncthreads();
        }
    }

    float dn = 0.f;
    int lo = 0, hi = 0;
    float y[8];
    if (t < GN) {
        float dsv = sd[t];
        int L = 0, R = t;
        while (L < R) { int m = (L + R) >> 1; float df = dsv - sd[m];
                        if (df * df < 0.01f) R = m; else L = m + 1; }
        lo = L;
        L = t + 1; R = GN;
        while (L < R) { int m = (L + R) >> 1; float df = dsv - sd[m];
                        if (df * df < 0.01f) L = m + 1; else R = m; }
        hi = L;
        dn = rsqrtf((float)(hi - lo));
        int orig = si[t];
        const float4* xp = reinterpret_cast<const float4*>(xg + (size_t)b * 6000 + orig * 8);
        float4 a4 = xp[0], c4 = xp[1];
        float xv[8] = {a4.x, a4.y, a4.z, a4.w, c4.x, c4.y, c4.z, c4.w};
        #pragma unroll
        for (int f = 0; f < 8; f++) {
            float s = 0.f;
            #pragma unroll
            for (int fp = 0; fp < 8; fp++) s = fmaf(xv[fp], wgs[fp * 8 + f], s);
            y[f] = s * dn;
        }
    } else {
        #pragma unroll
        for (int f = 0; f < 8; f++) y[f] = 0.f;
    }

    int lane = t & 31, wrp = t >> 5;
    #pragma unroll
    for (int f = 0; f < 8; f++) {
        float v = y[f];
        #pragma unroll
        for (int d = 1; d < 32; d <<= 1) {
            float o = __shfl_up_sync(0xffffffffu, v, d);
            if (lane >= d) v += o;
        }
        y[f] = v;
    }
    if (lane == 31) {
        #pragma unroll
        for (int f = 0; f < 8; f++) wsum[wrp][f] = y[f];
    }
    __syncthreads();
    if (t < 8) {
        float run = 0.f;
        for (int w = 0; w < 24; w++) { float x = wsum[w][t]; wsum[w][t] = run; run += x; }
    }
    __syncthreads();
    if (t < GN) {
        #pragma unroll
        for (int f = 0; f < 8; f++) pre[(t + 1) * 8 + f] = y[f] + wsum[wrp][f];
    }
    if (t < 8) pre[t] = 0.f;
    __syncthreads();

    if (t < GN) {
        float sc = INV_BN * g1[0], sh = be1[0];
        float gsum = 0.f;
        #pragma unroll
        for (int f = 0; f < 8; f++) {
            float s = pre[hi * 8 + f] - pre[lo * 8 + f];
            float hv = fmaf(dn, s, bg[f]);
            hv = fmaf(hv, sc, sh);
            gsum += fmaxf(hv, 0.f);
        }
        g_xcat[b * 1000 + 250 + si[t]] = gsum * 0.125f;
    }
}

// ---------------------------------------------------------------------------
// K3: conv1 (1->32, k=5, pad=2) + bn + relu + maxpool2 : [64,1,1000] -> [64,32,500]
// grid (64, 4): pooled tile of 125
// ---------------------------------------------------------------------------
__global__ void k_conv1(const float* __restrict__ Wc1, const float* __restrict__ bc1,
                        const float* __restrict__ gc1, const float* __restrict__ bec1) {
    int b = blockIdx.x, pt = blockIdx.y;
    int p0 = pt * 125;
    __shared__ float xs2[256];
    __shared__ float w[160], bb[32], gg[32], be[32];
    int t = threadIdx.x;
    for (int m = t; m < 254; m += 256) {
        int q = 2 * p0 - 2 + m;
        xs2[m] = (q >= 0 && q < 1000) ? g_xcat[b * 1000 + q] : 0.f;
    }
    if (t < 160) w[t] = Wc1[t];
    if (t < 32) { bb[t] = bc1[t]; gg[t] = gc1[t] * INV_BN; be[t] = bec1[t]; }
    __syncthreads();
    for (int idx = t; idx < 32 * 125; idx += 256) {
        int c = idx / 125, p = idx - c * 125;
        int m = 2 * p;
        float v0 = bb[c], v1 = bb[c];
        #pragma unroll
        for (int k = 0; k < 5; k++) {
            float wk = w[c * 5 + k];
            v0 = fmaf(xs2[m + k],     wk, v0);
            v1 = fmaf(xs2[m + 1 + k], wk, v1);
        }
        v0 = fmaf(v0, gg[c], be[c]);
        v1 = fmaf(v1, gg[c], be[c]);
        g_pool1[(b * 32 + c) * 500 + p0 + p] = fmaxf(fmaxf(v0, v1), 0.f);
    }
}

// ---------------------------------------------------------------------------
// K4: conv2 (32->64, k=5, pad=2) + bn + relu + maxpool2 : [64,32,500] -> [64,64,250]
// grid (b=64, pt=4 (64 pooled), oh=2 (32 oc)), 64 threads.
// f32x2 lanes = ADJACENT CONV POSITIONS (the maxpool pair). x stored as
// even/odd phase pair arrays (no duplication!):
//   sxe[ic][j] = (x[2(p0+j)-2], x[2(p0+j)-1]),  sxo[ic][j] = (x[2(p0+j)-1], x[2(p0+j)])
// tap k for pooled p0+j uses: k0->e[j], k1->o[j], k2->e[j+1], k3->o[j+1], k4->e[j+2].
// Thread tile: 4 oc x 8 pooled. Weights transposed [j][oc] in smem (conflict-free).
// ---------------------------------------------------------------------------
__global__ void __launch_bounds__(64) k_conv2(
        const float* __restrict__ Wc2, const float* __restrict__ bc2,
        const float* __restrict__ gc2, const float* __restrict__ bec2) {
    int b = blockIdx.x, pt = blockIdx.y, oh = blockIdx.z;
    int p0 = pt * 64;            // pooled start
    int oc0 = oh * 32;
    __shared__ float swt[160][33];                 // [ic*5+k][oc_local], padded
    __shared__ __align__(16) float2 sxe[8][66];    // ic-chunk of 8
    __shared__ __align__(16) float2 sxo[8][66];
    int t = threadIdx.x;
    int ocg = t & 7;             // oc_local base = 4*ocg
    int pg  = t >> 3;            // pooled base j0 = 8*pg (0..7)

    for (int i = t; i < 5120; i += 64) {
        int o = i / 160, j = i - o * 160;
        swt[j][o] = Wc2[(oc0 + o) * 160 + j];
    }

    ull acc[4][8];
    #pragma unroll
    for (int oo = 0; oo < 4; oo++)
        #pragma unroll
        for (int j = 0; j < 8; j++) acc[oo][j] = 0ull;

    for (int c = 0; c < 4; c++) {           // ic chunks of 8
        __syncthreads();
        for (int i = t; i < 1056; i += 64) {
            int half = i / 528;             // 0 = e, 1 = o
            int r = i - half * 528;
            int ic = r / 66, j = r - ic * 66;
            int q0 = 2 * (p0 + j) - 2 + half;
            const float* src = g_pool1 + (b * 32 + c * 8 + ic) * 500;
            float v0 = (q0 >= 0 && q0 < 500) ? src[q0] : 0.f;
            int q1 = q0 + 1;
            float v1 = (q1 >= 0 && q1 < 500) ? src[q1] : 0.f;
            if (half == 0) sxe[ic][j] = make_float2(v0, v1);
            else           sxo[ic][j] = make_float2(v0, v1);
        }
        __syncthreads();
        #pragma unroll 2
        for (int i8 = 0; i8 < 8; i8++) {
            int ic = c * 8 + i8;
            ull e[10], o[10];
            const ulonglong2* ep = reinterpret_cast<const ulonglong2*>(&sxe[i8][8 * pg]);
            const ulonglong2* op = reinterpret_cast<const ulonglong2*>(&sxo[i8][8 * pg]);
            #pragma unroll
            for (int q = 0; q < 5; q++) {
                ulonglong2 ve = ep[q]; e[2 * q] = ve.x; e[2 * q + 1] = ve.y;
                ulonglong2 vo = op[q]; o[2 * q] = vo.x; o[2 * q + 1] = vo.y;
            }
            #pragma unroll
            for (int oo = 0; oo < 4; oo++) {
                int ol = 4 * ocg + oo;
                float w0 = swt[ic * 5 + 0][ol];
                float w1 = swt[ic * 5 + 1][ol];
                float w2 = swt[ic * 5 + 2][ol];
                float w3 = swt[ic * 5 + 3][ol];
                float w4 = swt[ic * 5 + 4][ol];
                ull wd0 = pk2(w0, w0), wd1 = pk2(w1, w1), wd2 = pk2(w2, w2);
                ull wd3 = pk2(w3, w3), wd4 = pk2(w4, w4);
                #pragma unroll
                for (int j = 0; j < 8; j++) {
                    ull a = acc[oo][j];
                    a = fma2(e[j],     wd0, a);
                    a = fma2(o[j],     wd1, a);
                    a = fma2(e[j + 1], wd2, a);
                    a = fma2(o[j + 1], wd3, a);
                    a = fma2(e[j + 2], wd4, a);
                    acc[oo][j] = a;
                }
            }
        }
    }

    // epilogue: +bias, bn, relu, maxpool pair
    #pragma unroll
    for (int oo = 0; oo < 4; oo++) {
        int oc = oc0 + 4 * ocg + oo;
        float bb = bc2[oc];
        float gg = gc2[oc] * INV_BN;
        float be = bec2[oc];
        #pragma unroll
        for (int j = 0; j < 8; j++) {
            float2 a = upk2(acc[oo][j]);
            float r = fmaxf(fmaxf(fmaf(a.x + bb, gg, be), fmaf(a.y + bb, gg, be)), 0.f);
            int p = p0 + 8 * pg + j;
            if (p < 250) g_pool2[(b * 64 + oc) * 250 + p] = r;
        }
    }
}

// ---------------------------------------------------------------------------
// K5: conv3 K-split GEMM: part[ks][b][oc] = sum_{k in 64-chunk} X[b][k]*W[oc][k]
// grid 250 K-splits, 128 threads. f32x2 lanes = ADJACENT BATCH pair (x loads
// are natural float2, no duplication). Thread tile 8 b x 8 oc; thread's ocs
// are strided by 16 (oc = og + 16*o) so scalar w loads are conflict-free.
// ---------------------------------------------------------------------------
__global__ void __launch_bounds__(128) k_conv3(const float* __restrict__ Wc3) {
    int ks = blockIdx.x;       // 0..249
    int t = threadIdx.x;
    int og = t & 15;           // oc = og + 16*o, o=0..7
    int bg = t >> 4;           // b0 = 8*bg
    __shared__ float Xs[32][66];    // [kk][b], pad 66 (2-way STS conflicts only)
    __shared__ float Ws[32][130];   // [kk][oc], pad 130

    ull acc[8][4];
    #pragma unroll
    for (int o = 0; o < 8; o++)
        #pragma unroll
        for (int j = 0; j < 4; j++) acc[o][j] = 0ull;

    for (int c = 0; c < 2; c++) {
        int k0 = ks * 64 + c * 32;
        __syncthreads();
        for (int i = t; i < 2048; i += 128) {
            int bb = i >> 5, kk = i & 31;
            Xs[kk][bb] = g_pool2[bb * 16000 + k0 + kk];
        }
        for (int i = t; i < 4096; i += 128) {
            int oc = i >> 5, kk = i & 31;
            Ws[kk][oc] = Wc3[oc * 16000 + k0 + kk];
        }
        __syncthreads();
        #pragma unroll 4
        for (int kk = 0; kk < 32; kk++) {
            const ull* xq = reinterpret_cast<const ull*>(&Xs[kk][8 * bg]);
            ull x0 = xq[0], x1 = xq[1], x2 = xq[2], x3 = xq[3];
            ull wd[8];
            #pragma unroll
            for (int o = 0; o < 8; o++) {
                float wv = Ws[kk][og + 16 * o];
                wd[o] = pk2(wv, wv);
            }
            #pragma unroll
            for (int o = 0; o < 8; o++) {
                acc[o][0] = fma2(x0, wd[o], acc[o][0]);
                acc[o][1] = fma2(x1, wd[o], acc[o][1]);
                acc[o][2] = fma2(x2, wd[o], acc[o][2]);
                acc[o][3] = fma2(x3, wd[o], acc[o][3]);
            }
        }
    }
    #pragma unroll
    for (int o = 0; o < 8; o++) {
        int oc = og + 16 * o;
        #pragma unroll
        for (int j = 0; j < 4; j++) {
            float2 v = upk2(acc[o][j]);
            int bb = 8 * bg + 2 * j;
            g_part3[(ks * 64 + bb) * 128 + oc]       = v.x;
            g_part3[(ks * 64 + bb + 1) * 128 + oc]   = v.y;
        }
    }
}

// ---------------------------------------------------------------------------
// K6: reduce partials (+bc3), FC 128->64 (+bn relu), FC 64->12, log_softmax
// one block per batch, 128 threads
// ---------------------------------------------------------------------------
__global__ void k_fc(const float* __restrict__ bc3, const float* __restrict__ Wf,
                     const float* __restrict__ bf, const float* __restrict__ gf,
                     const float* __restrict__ bef, const float* __restrict__ Wo,
                     const float* __restrict__ bo, float* __restrict__ out) {
    int b = blockIdx.x;
    int t = threadIdx.x;
    __shared__ float f[128], u[64], o[12];
    {
        float s0 = 0.f, s1 = 0.f;
        #pragma unroll 5
        for (int ks = 0; ks < 250; ks += 2) {
            s0 += g_part3[((ks + 0) * 64 + b) * 128 + t];
            s1 += g_part3[((ks + 1) * 64 + b) * 128 + t];
        }
        f[t] = bc3[t] + (s0 + s1);
    }
    __syncthreads();
    if (t < 64) {
        float z = bf[t];
        #pragma unroll 8
        for (int k = 0; k < 128; k++) z = fmaf(f[k], Wf[k * 64 + t], z);
        z = z * (INV_BN * gf[t]) + bef[t];
        u[t] = fmaxf(z, 0.f);
    }
    __syncthreads();
    if (t < 12) {
        float z = bo[t];
        #pragma unroll 8
        for (int k = 0; k < 64; k++) z = fmaf(u[k], Wo[k * 12 + t], z);
        o[t] = z;
    }
    __syncthreads();
    if (t < 12) {
        float m = o[0];
        #pragma unroll
        for (int i = 1; i < 12; i++) m = fmaxf(m, o[i]);
        float s = 0.f;
        #pragma unroll
        for (int i = 0; i < 12; i++) s += expf(o[i] - m);
        out[b * 12 + t] = (o[t] - m) - logf(s);
    }
}

// ---------------------------------------------------------------------------
extern "C" void kernel_launch(void* const* d_in, const int* in_sizes, int n_in,
                              void* d_out, int out_size) {
    const float* x_sample = (const float*)d_in[0];
    const float* x_graph  = (const float*)d_in[1];
    const float* W1   = (const float*)d_in[2];
    const float* b1   = (const float*)d_in[3];
    const float* gl   = (const float*)d_in[4];
    const float* bl   = (const float*)d_in[5];
    const float* Wg   = (const float*)d_in[6];
    const float* bg   = (const float*)d_in[7];
    const float* g1   = (const float*)d_in[8];
    const float* be1  = (const float*)d_in[9];
    const float* Wc1  = (const float*)d_in[10];
    const float* bc1  = (const float*)d_in[11];
    const float* gc1  = (const float*)d_in[12];
    const float* bec1 = (const float*)d_in[13];
    const float* Wc2  = (const float*)d_in[14];
    const float* bc2  = (const float*)d_in[15];
    const float* gc2  = (const float*)d_in[16];
    const float* bec2 = (const float*)d_in[17];
    const float* Wc3  = (const float*)d_in[18];
    const float* bc3  = (const float*)d_in[19];
    const float* Wf   = (const float*)d_in[20];
    const float* bf   = (const float*)d_in[21];
    const float* gf   = (const float*)d_in[22];
    const float* bef  = (const float*)d_in[23];
    const float* Wo   = (const float*)d_in[24];
    const float* bo   = (const float*)d_in[25];
    float* out = (float*)d_out;

    k_front<<<128, 768>>>(x_sample, W1, b1, gl, bl, x_graph, Wg, bg, g1, be1);
    k_conv1<<<dim3(64, 4), 256>>>(Wc1, bc1, gc1, bec1);
    k_conv2<<<dim3(64, 4, 2), 64>>>(Wc2, bc2, gc2, bec2);
    k_conv3<<<250, 128>>>(Wc3);
    k_fc   <<<64, 128>>>(bc3, Wf, bf, gf, bef, Wo, bo, out);
}

// round 5
// speedup vs baseline: 2.8474x; 1.1103x over previous
#include <cuda_runtime.h>
#include <cuda_bf16.h>

// ---------------------------------------------------------------------------
// Model_2 : FC -> graph conv (threshold adjacency) -> conv1d x3 -> FC -> logsoftmax
// B=64, N=750, F=8, NF=250
// ---------------------------------------------------------------------------

#define INV_BN 0.9999950000374997f   // 1/sqrt(1 + 1e-5)
#define GN 750

typedef unsigned long long ull;

// Scratch (device globals; no dynamic allocation allowed)
__device__ float g_xcat[64 * 1000];          // concat [s(250) | g(750)] per batch
__device__ float g_pool1[64 * 32 * 500];     // after conv1+bn+relu+pool
__device__ float g_pool2[64 * 64 * 250];     // after conv2+bn+relu+pool
__device__ float g_part3[250 * 64 * 128];    // conv3 K-split partials [ks][b][oc]

// ---- packed f32x2 helpers (sm_100+ : 2x fp32 FMA throughput) ----------------
__device__ __forceinline__ ull pk2(float lo, float hi) {
    ull r;
    asm("mov.b64 %0, {%1,%2};" : "=l"(r) : "f"(lo), "f"(hi));
    return r;
}
__device__ __forceinline__ ull fma2(ull a, ull b, ull c) {
    ull d;
    asm("fma.rn.f32x2 %0, %1, %2, %3;" : "=l"(d) : "l"(a), "l"(b), "l"(c));
    return d;
}
__device__ __forceinline__ float2 upk2(ull v) {
    float2 r;
    asm("mov.b64 {%0,%1}, %2;" : "=f"(r.x), "=f"(r.y) : "l"(v));
    return r;
}

// ---------------------------------------------------------------------------
// K_front: blocks 0..63 -> graph conv per batch; blocks 64..127 -> linear1.
// Graph: hybrid bitonic sort (regs + shfl for j<32, smem for j>=32) + exact
// interval search + prefix sums. (diff*diff < 0.01f) is monotone in |diff| in
// fp32 -> adjacency = contiguous interval in sorted order; binary search with
// the IDENTICAL predicate reproduces the exact reference edge set.
// ---------------------------------------------------------------------------
__global__ void __launch_bounds__(1024) k_front(
        const float* __restrict__ xs, const float* __restrict__ W1,
        const float* __restrict__ b1, const float* __restrict__ gl,
        const float* __restrict__ bl,
        const float* __restrict__ xg, const float* __restrict__ Wg,
        const float* __restrict__ bg, const float* __restrict__ g1,
        const float* __restrict__ be1) {
    int t = threadIdx.x;
    __shared__ float sd[1024];
    __shared__ int   si[1024];
    __shared__ float pre[751 * 8];
    __shared__ float wsum[32][8];
    __shared__ float wgs[64];

    if (blockIdx.x >= 64) {
        // ------- linear1 path -------
        int b = blockIdx.x - 64;
        if (t < 250) sd[t] = xs[b * 250 + t];
        __syncthreads();
        if (t < 250) {
            float acc = 0.f;
            #pragma unroll 5
            for (int k = 0; k < 250; k++) acc = fmaf(sd[k], W1[k * 250 + t], acc);
            float v = (acc + b1[t]) * (INV_BN * gl[t]) + bl[t];
            g_xcat[b * 1000 + t] = fmaxf(v, 0.f);
        }
        return;
    }

    // ------- graph path -------
    int b = blockIdx.x;
    float key;
    int   pay;
    if (t < GN) { key = xg[b * 6000 + t * 8]; pay = t; }
    else        { key = __int_as_float(0x7f800000); pay = -1; }
    if (t < 64) wgs[t] = Wg[t];

    // hybrid bitonic sort ascending, 1 element per thread
    for (int k2 = 2; k2 <= 1024; k2 <<= 1) {
        bool up = ((t & k2) == 0);
        for (int j = k2 >> 1; j > 0; j >>= 1) {
            float kq; int pq;
            if (j >= 32) {
                __syncthreads();
                sd[t] = key; si[t] = pay;
                __syncthreads();
                kq = sd[t ^ j]; pq = si[t ^ j];
            } else {
                kq = __shfl_xor_sync(0xffffffffu, key, j);
                pq = __shfl_xor_sync(0xffffffffu, pay, j);
            }
            bool lower = (t & j) == 0;
            float a = lower ? key : kq;   // value at lower index
            float c = lower ? kq : key;   // value at upper index
            bool sw = up ? (a > c) : (a < c);   // strict, matches reference ties
            if (sw) { key = kq; pay = pq; }
        }
    }
    __syncthreads();
    sd[t] = key; si[t] = pay;
    __syncthreads();

    float dn = 0.f;
    int lo = 0, hi = 0;
    float y[8];
    if (t < GN) {
        float dsv = key;
        int L = 0, R = t;
        while (L < R) { int m = (L + R) >> 1; float df = dsv - sd[m];
                        if (df * df < 0.01f) R = m; else L = m + 1; }
        lo = L;
        L = t + 1; R = GN;
        while (L < R) { int m = (L + R) >> 1; float df = dsv - sd[m];
                        if (df * df < 0.01f) L = m + 1; else R = m; }
        hi = L;
        dn = rsqrtf((float)(hi - lo));
        int orig = pay;
        const float4* xp = reinterpret_cast<const float4*>(xg + (size_t)b * 6000 + orig * 8);
        float4 a4 = xp[0], c4 = xp[1];
        float xv[8] = {a4.x, a4.y, a4.z, a4.w, c4.x, c4.y, c4.z, c4.w};
        #pragma unroll
        for (int f = 0; f < 8; f++) {
            float s = 0.f;
            #pragma unroll
            for (int fp = 0; fp < 8; fp++) s = fmaf(xv[fp], wgs[fp * 8 + f], s);
            y[f] = s * dn;
        }
    } else {
        #pragma unroll
        for (int f = 0; f < 8; f++) y[f] = 0.f;
    }

    int lane = t & 31, wrp = t >> 5;
    #pragma unroll
    for (int f = 0; f < 8; f++) {
        float v = y[f];
        #pragma unroll
        for (int d = 1; d < 32; d <<= 1) {
            float o = __shfl_up_sync(0xffffffffu, v, d);
            if (lane >= d) v += o;
        }
        y[f] = v;
    }
    if (lane == 31) {
        #pragma unroll
        for (int f = 0; f < 8; f++) wsum[wrp][f] = y[f];
    }
    __syncthreads();
    if (t < 8) {
        float run = 0.f;
        for (int w = 0; w < 32; w++) { float x = wsum[w][t]; wsum[w][t] = run; run += x; }
    }
    __syncthreads();
    if (t < GN) {
        #pragma unroll
        for (int f = 0; f < 8; f++) pre[(t + 1) * 8 + f] = y[f] + wsum[wrp][f];
    }
    if (t < 8) pre[t] = 0.f;
    __syncthreads();

    if (t < GN) {
        float sc = INV_BN * g1[0], sh = be1[0];
        float gsum = 0.f;
        #pragma unroll
        for (int f = 0; f < 8; f++) {
            float s = pre[hi * 8 + f] - pre[lo * 8 + f];
            float hv = fmaf(dn, s, bg[f]);
            hv = fmaf(hv, sc, sh);
            gsum += fmaxf(hv, 0.f);
        }
        g_xcat[b * 1000 + 250 + pay] = gsum * 0.125f;
    }
}

// ---------------------------------------------------------------------------
// K3: conv1 (1->32, k=5, pad=2) + bn + relu + maxpool2 : [64,1,1000] -> [64,32,500]
// grid (64, 4): pooled tile of 125
// ---------------------------------------------------------------------------
__global__ void k_conv1(const float* __restrict__ Wc1, const float* __restrict__ bc1,
                        const float* __restrict__ gc1, const float* __restrict__ bec1) {
    int b = blockIdx.x, pt = blockIdx.y;
    int p0 = pt * 125;
    __shared__ float xs2[256];
    __shared__ float w[160], bb[32], gg[32], be[32];
    int t = threadIdx.x;
    for (int m = t; m < 254; m += 256) {
        int q = 2 * p0 - 2 + m;
        xs2[m] = (q >= 0 && q < 1000) ? g_xcat[b * 1000 + q] : 0.f;
    }
    if (t < 160) w[t] = Wc1[t];
    if (t < 32) { bb[t] = bc1[t]; gg[t] = gc1[t] * INV_BN; be[t] = bec1[t]; }
    __syncthreads();
    for (int idx = t; idx < 32 * 125; idx += 256) {
        int c = idx / 125, p = idx - c * 125;
        int m = 2 * p;
        float v0 = bb[c], v1 = bb[c];
        #pragma unroll
        for (int k = 0; k < 5; k++) {
            float wk = w[c * 5 + k];
            v0 = fmaf(xs2[m + k],     wk, v0);
            v1 = fmaf(xs2[m + 1 + k], wk, v1);
        }
        v0 = fmaf(v0, gg[c], be[c]);
        v1 = fmaf(v1, gg[c], be[c]);
        g_pool1[(b * 32 + c) * 500 + p0 + p] = fmaxf(fmaxf(v0, v1), 0.f);
    }
}

// ---------------------------------------------------------------------------
// K4: conv2 (32->64, k=5, pad=2) + bn + relu + maxpool2 : [64,32,500] -> [64,64,250]
// grid (b=64, pt=4 (64 pooled), oh=2 (32 oc)), 64 threads.
// f32x2 lanes = adjacent conv positions (the maxpool pair), even/odd phase
// pair arrays (no duplication). Thread tile: 4 oc x 8 pooled.
// ---------------------------------------------------------------------------
__global__ void __launch_bounds__(64) k_conv2(
        const float* __restrict__ Wc2, const float* __restrict__ bc2,
        const float* __restrict__ gc2, const float* __restrict__ bec2) {
    int b = blockIdx.x, pt = blockIdx.y, oh = blockIdx.z;
    int p0 = pt * 64;            // pooled start
    int oc0 = oh * 32;
    __shared__ float swt[160][33];                 // [ic*5+k][oc_local], padded
    __shared__ __align__(16) float2 sxe[8][66];    // ic-chunk of 8
    __shared__ __align__(16) float2 sxo[8][66];
    int t = threadIdx.x;
    int ocg = t & 7;             // oc_local base = 4*ocg
    int pg  = t >> 3;            // pooled base j0 = 8*pg (0..7)

    for (int i = t; i < 5120; i += 64) {
        int o = i / 160, j = i - o * 160;
        swt[j][o] = Wc2[(oc0 + o) * 160 + j];
    }

    ull acc[4][8];
    #pragma unroll
    for (int oo = 0; oo < 4; oo++)
        #pragma unroll
        for (int j = 0; j < 8; j++) acc[oo][j] = 0ull;

    for (int c = 0; c < 4; c++) {           // ic chunks of 8
        __syncthreads();
        for (int i = t; i < 1056; i += 64) {
            int half = i / 528;             // 0 = e, 1 = o
            int r = i - half * 528;
            int ic = r / 66, j = r - ic * 66;
            int q0 = 2 * (p0 + j) - 2 + half;
            const float* src = g_pool1 + (b * 32 + c * 8 + ic) * 500;
            float v0 = (q0 >= 0 && q0 < 500) ? src[q0] : 0.f;
            int q1 = q0 + 1;
            float v1 = (q1 >= 0 && q1 < 500) ? src[q1] : 0.f;
            if (half == 0) sxe[ic][j] = make_float2(v0, v1);
            else           sxo[ic][j] = make_float2(v0, v1);
        }
        __syncthreads();
        #pragma unroll 2
        for (int i8 = 0; i8 < 8; i8++) {
            int ic = c * 8 + i8;
            ull e[10], o[10];
            const ulonglong2* ep = reinterpret_cast<const ulonglong2*>(&sxe[i8][8 * pg]);
            const ulonglong2* op = reinterpret_cast<const ulonglong2*>(&sxo[i8][8 * pg]);
            #pragma unroll
            for (int q = 0; q < 5; q++) {
                ulonglong2 ve = ep[q]; e[2 * q] = ve.x; e[2 * q + 1] = ve.y;
                ulonglong2 vo = op[q]; o[2 * q] = vo.x; o[2 * q + 1] = vo.y;
            }
            #pragma unroll
            for (int oo = 0; oo < 4; oo++) {
                int ol = 4 * ocg + oo;
                float w0 = swt[ic * 5 + 0][ol];
                float w1 = swt[ic * 5 + 1][ol];
                float w2 = swt[ic * 5 + 2][ol];
                float w3 = swt[ic * 5 + 3][ol];
                float w4 = swt[ic * 5 + 4][ol];
                ull wd0 = pk2(w0, w0), wd1 = pk2(w1, w1), wd2 = pk2(w2, w2);
                ull wd3 = pk2(w3, w3), wd4 = pk2(w4, w4);
                #pragma unroll
                for (int j = 0; j < 8; j++) {
                    ull a = acc[oo][j];
                    a = fma2(e[j],     wd0, a);
                    a = fma2(o[j],     wd1, a);
                    a = fma2(e[j + 1], wd2, a);
                    a = fma2(o[j + 1], wd3, a);
                    a = fma2(e[j + 2], wd4, a);
                    acc[oo][j] = a;
                }
            }
        }
    }

    #pragma unroll
    for (int oo = 0; oo < 4; oo++) {
        int oc = oc0 + 4 * ocg + oo;
        float bb = bc2[oc];
        float gg = gc2[oc] * INV_BN;
        float be = bec2[oc];
        #pragma unroll
        for (int j = 0; j < 8; j++) {
            float2 a = upk2(acc[oo][j]);
            float r = fmaxf(fmaxf(fmaf(a.x + bb, gg, be), fmaf(a.y + bb, gg, be)), 0.f);
            int p = p0 + 8 * pg + j;
            if (p < 250) g_pool2[(b * 64 + oc) * 250 + p] = r;
        }
    }
}

// ---------------------------------------------------------------------------
// K5: conv3 K-split GEMM: part[ks][b][oc] = sum_{k in 64-chunk} X[b][k]*W[oc][k]
// grid 250 K-splits, 256 threads (8 warps). Whole chunk resident in smem,
// ONE sync, straight fma2 loop. f32x2 lanes = adjacent batch pair.
// Thread tile 8 b x 4 oc; oc strided by 32 -> conflict-free scalar w loads.
// ---------------------------------------------------------------------------
__global__ void __launch_bounds__(256) k_conv3(const float* __restrict__ Wc3) {
    int ks = blockIdx.x;       // 0..249
    int t = threadIdx.x;
    __shared__ __align__(16) float Xs[64][68];   // [kk][b], pad 68 (16B-aligned rows)
    __shared__ float Ws[64][133];                // [kk][oc], pad 133 (conflict-free)
    int og = t & 31;           // oc = og + 32*o, o=0..3
    int bg = t >> 5;           // warp id -> b0 = 8*bg (x loads warp-broadcast)
    int k0 = ks * 64;

    for (int i = t; i < 4096; i += 256) {
        int bb = i >> 6, kk = i & 63;
        Xs[kk][bb] = g_pool2[bb * 16000 + k0 + kk];
    }
    for (int i = t; i < 8192; i += 256) {
        int oc = i >> 6, kk = i & 63;
        Ws[kk][oc] = Wc3[oc * 16000 + k0 + kk];
    }
    __syncthreads();

    ull acc[4][4];
    #pragma unroll
    for (int o = 0; o < 4; o++)
        #pragma unroll
        for (int j = 0; j < 4; j++) acc[o][j] = 0ull;

    #pragma unroll 4
    for (int kk = 0; kk < 64; kk++) {
        const ull* xq = reinterpret_cast<const ull*>(&Xs[kk][8 * bg]);
        ull x0 = xq[0], x1 = xq[1], x2 = xq[2], x3 = xq[3];
        #pragma unroll
        for (int o = 0; o < 4; o++) {
            float wv = Ws[kk][og + 32 * o];
            ull wd = pk2(wv, wv);
            acc[o][0] = fma2(x0, wd, acc[o][0]);
            acc[o][1] = fma2(x1, wd, acc[o][1]);
            acc[o][2] = fma2(x2, wd, acc[o][2]);
            acc[o][3] = fma2(x3, wd, acc[o][3]);
        }
    }

    #pragma unroll
    for (int o = 0; o < 4; o++) {
        int oc = og + 32 * o;
        #pragma unroll
        for (int j = 0; j < 4; j++) {
            float2 v = upk2(acc[o][j]);
            int bb = 8 * bg + 2 * j;
            g_part3[(ks * 64 + bb) * 128 + oc]     = v.x;
            g_part3[(ks * 64 + bb + 1) * 128 + oc] = v.y;
        }
    }
}

// ---------------------------------------------------------------------------
// K6: reduce partials (+bc3) with 4-way split-K, FC 128->64 (+bn relu),
// FC 64->12, log_softmax. one block per batch, 512 threads.
// ---------------------------------------------------------------------------
__global__ void __launch_bounds__(512) k_fc(
        const float* __restrict__ bc3, const float* __restrict__ Wf,
        const float* __restrict__ bf, const float* __restrict__ gf,
        const float* __restrict__ bef, const float* __restrict__ Wo,
        const float* __restrict__ bo, float* __restrict__ out) {
    int b = blockIdx.x;
    int t = threadIdx.x;
    __shared__ float red[4][128];
    __shared__ float f[128], u[64], o[12];
    {
        int oc = t & 127, r = t >> 7;      // r = 0..3
        float s = 0.f;
        #pragma unroll 2
        for (int ks = r; ks < 250; ks += 4)
            s += g_part3[(ks * 64 + b) * 128 + oc];
        red[r][oc] = s;
    }
    __syncthreads();
    if (t < 128) f[t] = bc3[t] + ((red[0][t] + red[1][t]) + (red[2][t] + red[3][t]));
    __syncthreads();
    if (t < 64) {
        float z = bf[t];
        #pragma unroll 8
        for (int k = 0; k < 128; k++) z = fmaf(f[k], Wf[k * 64 + t], z);
        z = z * (INV_BN * gf[t]) + bef[t];
        u[t] = fmaxf(z, 0.f);
    }
    __syncthreads();
    if (t < 12) {
        float z = bo[t];
        #pragma unroll 8
        for (int k = 0; k < 64; k++) z = fmaf(u[k], Wo[k * 12 + t], z);
        o[t] = z;
    }
    __syncthreads();
    if (t < 12) {
        float m = o[0];
        #pragma unroll
        for (int i = 1; i < 12; i++) m = fmaxf(m, o[i]);
        float s = 0.f;
        #pragma unroll
        for (int i = 0; i < 12; i++) s += expf(o[i] - m);
        out[b * 12 + t] = (o[t] - m) - logf(s);
    }
}

// ---------------------------------------------------------------------------
extern "C" void kernel_launch(void* const* d_in, const int* in_sizes, int n_in,
                              void* d_out, int out_size) {
    const float* x_sample = (const float*)d_in[0];
    const float* x_graph  = (const float*)d_in[1];
    const float* W1   = (const float*)d_in[2];
    const float* b1   = (const float*)d_in[3];
    const float* gl   = (const float*)d_in[4];
    const float* bl   = (const float*)d_in[5];
    const float* Wg   = (const float*)d_in[6];
    const float* bg   = (const float*)d_in[7];
    const float* g1   = (const float*)d_in[8];
    const float* be1  = (const float*)d_in[9];
    const float* Wc1  = (const float*)d_in[10];
    const float* bc1  = (const float*)d_in[11];
    const float* gc1  = (const float*)d_in[12];
    const float* bec1 = (const float*)d_in[13];
    const float* Wc2  = (const float*)d_in[14];
    const float* bc2  = (const float*)d_in[15];
    const float* gc2  = (const float*)d_in[16];
    const float* bec2 = (const float*)d_in[17];
    const float* Wc3  = (const float*)d_in[18];
    const float* bc3  = (const float*)d_in[19];
    const float* Wf   = (const float*)d_in[20];
    const float* bf   = (const float*)d_in[21];
    const float* gf   = (const float*)d_in[22];
    const float* bef  = (const float*)d_in[23];
    const float* Wo   = (const float*)d_in[24];
    const float* bo   = (const float*)d_in[25];
    float* out = (float*)d_out;

    k_front<<<128, 1024>>>(x_sample, W1, b1, gl, bl, x_graph, Wg, bg, g1, be1);
    k_conv1<<<dim3(64, 4), 256>>>(Wc1, bc1, gc1, bec1);
    k_conv2<<<dim3(64, 4, 2), 64>>>(Wc2, bc2, gc2, bec2);
    k_conv3<<<250, 256>>>(Wc3);
    k_fc   <<<64, 512>>>(bc3, Wf, bf, gf, bef, Wo, bo, out);
}

// round 6
// speedup vs baseline: 3.2006x; 1.1240x over previous
#include <cuda_runtime.h>
#include <cuda_bf16.h>

// ---------------------------------------------------------------------------
// Model_2 : FC -> graph conv (threshold adjacency) -> conv1d x3 -> FC -> logsoftmax
// B=64, N=750, F=8, NF=250
// ---------------------------------------------------------------------------

#define INV_BN 0.9999950000374997f   // 1/sqrt(1 + 1e-5)
#define GN 750

typedef unsigned long long ull;

// Scratch (device globals; no dynamic allocation allowed)
__device__ float g_xcat[64 * 1000];          // concat [s(250) | g(750)] per batch
__device__ float g_pool1[64 * 32 * 500];     // after conv1+bn+relu+pool
__device__ float g_pool2[64 * 64 * 250];     // after conv2+bn+relu+pool
__device__ float g_part3[250 * 64 * 128];    // conv3 K-split partials [ks][b][oc]

// ---- packed f32x2 helpers (sm_100+ : 2x fp32 FMA throughput) ----------------
__device__ __forceinline__ ull pk2(float lo, float hi) {
    ull r;
    asm("mov.b64 %0, {%1,%2};" : "=l"(r) : "f"(lo), "f"(hi));
    return r;
}
__device__ __forceinline__ ull fma2(ull a, ull b, ull c) {
    ull d;
    asm("fma.rn.f32x2 %0, %1, %2, %3;" : "=l"(d) : "l"(a), "l"(b), "l"(c));
    return d;
}
__device__ __forceinline__ float2 upk2(ull v) {
    float2 r;
    asm("mov.b64 {%0,%1}, %2;" : "=f"(r.x), "=f"(r.y) : "l"(v));
    return r;
}

// ---------------------------------------------------------------------------
// K_front: blocks 0..63 -> graph conv per batch; blocks 64..127 -> linear1.
// Graph: hybrid bitonic sort (regs + shfl for j<32, smem for j>=32) + exact
// interval search + prefix sums. (diff*diff < 0.01f) is monotone in |diff| in
// fp32 -> adjacency = contiguous interval in sorted order; binary search with
// the IDENTICAL predicate reproduces the exact reference edge set.
// ---------------------------------------------------------------------------
__global__ void __launch_bounds__(1024) k_front(
        const float* __restrict__ xs, const float* __restrict__ W1,
        const float* __restrict__ b1, const float* __restrict__ gl,
        const float* __restrict__ bl,
        const float* __restrict__ xg, const float* __restrict__ Wg,
        const float* __restrict__ bg, const float* __restrict__ g1,
        const float* __restrict__ be1) {
    int t = threadIdx.x;
    __shared__ float sd[1024];
    __shared__ int   si[1024];
    __shared__ float pre[751 * 8];
    __shared__ float wsum[32][8];
    __shared__ float wgs[64];

    if (blockIdx.x >= 64) {
        // ------- linear1 path -------
        int b = blockIdx.x - 64;
        if (t < 250) sd[t] = xs[b * 250 + t];
        __syncthreads();
        if (t < 250) {
            float acc = 0.f;
            #pragma unroll 5
            for (int k = 0; k < 250; k++) acc = fmaf(sd[k], W1[k * 250 + t], acc);
            float v = (acc + b1[t]) * (INV_BN * gl[t]) + bl[t];
            g_xcat[b * 1000 + t] = fmaxf(v, 0.f);
        }
        return;
    }

    // ------- graph path -------
    int b = blockIdx.x;
    float key;
    int   pay;
    if (t < GN) { key = xg[b * 6000 + t * 8]; pay = t; }
    else        { key = __int_as_float(0x7f800000); pay = -1; }
    if (t < 64) wgs[t] = Wg[t];

    // hybrid bitonic sort ascending, 1 element per thread
    for (int k2 = 2; k2 <= 1024; k2 <<= 1) {
        bool up = ((t & k2) == 0);
        for (int j = k2 >> 1; j > 0; j >>= 1) {
            float kq; int pq;
            if (j >= 32) {
                __syncthreads();
                sd[t] = key; si[t] = pay;
                __syncthreads();
                kq = sd[t ^ j]; pq = si[t ^ j];
            } else {
                kq = __shfl_xor_sync(0xffffffffu, key, j);
                pq = __shfl_xor_sync(0xffffffffu, pay, j);
            }
            bool lower = (t & j) == 0;
            float a = lower ? key : kq;   // value at lower index
            float c = lower ? kq : key;   // value at upper index
            bool sw = up ? (a > c) : (a < c);   // strict, matches reference ties
            if (sw) { key = kq; pay = pq; }
        }
    }
    __syncthreads();
    sd[t] = key; si[t] = pay;
    __syncthreads();

    float dn = 0.f;
    int lo = 0, hi = 0;
    float y[8];
    if (t < GN) {
        float dsv = key;
        int L = 0, R = t;
        while (L < R) { int m = (L + R) >> 1; float df = dsv - sd[m];
                        if (df * df < 0.01f) R = m; else L = m + 1; }
        lo = L;
        L = t + 1; R = GN;
        while (L < R) { int m = (L + R) >> 1; float df = dsv - sd[m];
                        if (df * df < 0.01f) L = m + 1; else R = m; }
        hi = L;
        dn = rsqrtf((float)(hi - lo));
        int orig = pay;
        const float4* xp = reinterpret_cast<const float4*>(xg + (size_t)b * 6000 + orig * 8);
        float4 a4 = xp[0], c4 = xp[1];
        float xv[8] = {a4.x, a4.y, a4.z, a4.w, c4.x, c4.y, c4.z, c4.w};
        #pragma unroll
        for (int f = 0; f < 8; f++) {
            float s = 0.f;
            #pragma unroll
            for (int fp = 0; fp < 8; fp++) s = fmaf(xv[fp], wgs[fp * 8 + f], s);
            y[f] = s * dn;
        }
    } else {
        #pragma unroll
        for (int f = 0; f < 8; f++) y[f] = 0.f;
    }

    int lane = t & 31, wrp = t >> 5;
    #pragma unroll
    for (int f = 0; f < 8; f++) {
        float v = y[f];
        #pragma unroll
        for (int d = 1; d < 32; d <<= 1) {
            float o = __shfl_up_sync(0xffffffffu, v, d);
            if (lane >= d) v += o;
        }
        y[f] = v;
    }
    if (lane == 31) {
        #pragma unroll
        for (int f = 0; f < 8; f++) wsum[wrp][f] = y[f];
    }
    __syncthreads();
    if (t < 8) {
        float run = 0.f;
        for (int w = 0; w < 32; w++) { float x = wsum[w][t]; wsum[w][t] = run; run += x; }
    }
    __syncthreads();
    if (t < GN) {
        #pragma unroll
        for (int f = 0; f < 8; f++) pre[(t + 1) * 8 + f] = y[f] + wsum[wrp][f];
    }
    if (t < 8) pre[t] = 0.f;
    __syncthreads();

    if (t < GN) {
        float sc = INV_BN * g1[0], sh = be1[0];
        float gsum = 0.f;
        #pragma unroll
        for (int f = 0; f < 8; f++) {
            float s = pre[hi * 8 + f] - pre[lo * 8 + f];
            float hv = fmaf(dn, s, bg[f]);
            hv = fmaf(hv, sc, sh);
            gsum += fmaxf(hv, 0.f);
        }
        g_xcat[b * 1000 + 250 + pay] = gsum * 0.125f;
    }
}

// ---------------------------------------------------------------------------
// K3: conv1 (1->32, k=5, pad=2) + bn + relu + maxpool2 : [64,1,1000] -> [64,32,500]
// grid (64, 4): pooled tile of 125
// ---------------------------------------------------------------------------
__global__ void k_conv1(const float* __restrict__ Wc1, const float* __restrict__ bc1,
                        const float* __restrict__ gc1, const float* __restrict__ bec1) {
    int b = blockIdx.x, pt = blockIdx.y;
    int p0 = pt * 125;
    __shared__ float xs2[256];
    __shared__ float w[160], bb[32], gg[32], be[32];
    int t = threadIdx.x;
    for (int m = t; m < 254; m += 256) {
        int q = 2 * p0 - 2 + m;
        xs2[m] = (q >= 0 && q < 1000) ? g_xcat[b * 1000 + q] : 0.f;
    }
    if (t < 160) w[t] = Wc1[t];
    if (t < 32) { bb[t] = bc1[t]; gg[t] = gc1[t] * INV_BN; be[t] = bec1[t]; }
    __syncthreads();
    for (int idx = t; idx < 32 * 125; idx += 256) {
        int c = idx / 125, p = idx - c * 125;
        int m = 2 * p;
        float v0 = bb[c], v1 = bb[c];
        #pragma unroll
        for (int k = 0; k < 5; k++) {
            float wk = w[c * 5 + k];
            v0 = fmaf(xs2[m + k],     wk, v0);
            v1 = fmaf(xs2[m + 1 + k], wk, v1);
        }
        v0 = fmaf(v0, gg[c], be[c]);
        v1 = fmaf(v1, gg[c], be[c]);
        g_pool1[(b * 32 + c) * 500 + p0 + p] = fmaxf(fmaxf(v0, v1), 0.f);
    }
}

// ---------------------------------------------------------------------------
// K4: conv2 (32->64, k=5, pad=2) + bn + relu + maxpool2 : [64,32,500] -> [64,64,250]
// grid (b=64, pt=4 (64 pooled), oh=2 (32 oc)), 64 threads.
// f32x2 lanes = adjacent conv positions (the maxpool pair), even/odd phase
// pair arrays (no duplication). Thread tile: 4 oc x 8 pooled.
// ---------------------------------------------------------------------------
__global__ void __launch_bounds__(64) k_conv2(
        const float* __restrict__ Wc2, const float* __restrict__ bc2,
        const float* __restrict__ gc2, const float* __restrict__ bec2) {
    int b = blockIdx.x, pt = blockIdx.y, oh = blockIdx.z;
    int p0 = pt * 64;            // pooled start
    int oc0 = oh * 32;
    __shared__ float swt[160][33];                 // [ic*5+k][oc_local], padded
    __shared__ __align__(16) float2 sxe[8][66];    // ic-chunk of 8
    __shared__ __align__(16) float2 sxo[8][66];
    int t = threadIdx.x;
    int ocg = t & 7;             // oc_local base = 4*ocg
    int pg  = t >> 3;            // pooled base j0 = 8*pg (0..7)

    for (int i = t; i < 5120; i += 64) {
        int o = i / 160, j = i - o * 160;
        swt[j][o] = Wc2[(oc0 + o) * 160 + j];
    }

    ull acc[4][8];
    #pragma unroll
    for (int oo = 0; oo < 4; oo++)
        #pragma unroll
        for (int j = 0; j < 8; j++) acc[oo][j] = 0ull;

    for (int c = 0; c < 4; c++) {           // ic chunks of 8
        __syncthreads();
        for (int i = t; i < 1056; i += 64) {
            int half = i / 528;             // 0 = e, 1 = o
            int r = i - half * 528;
            int ic = r / 66, j = r - ic * 66;
            int q0 = 2 * (p0 + j) - 2 + half;
            const float* src = g_pool1 + (b * 32 + c * 8 + ic) * 500;
            float v0 = (q0 >= 0 && q0 < 500) ? src[q0] : 0.f;
            int q1 = q0 + 1;
            float v1 = (q1 >= 0 && q1 < 500) ? src[q1] : 0.f;
            if (half == 0) sxe[ic][j] = make_float2(v0, v1);
            else           sxo[ic][j] = make_float2(v0, v1);
        }
        __syncthreads();
        #pragma unroll 2
        for (int i8 = 0; i8 < 8; i8++) {
            int ic = c * 8 + i8;
            ull e[10], o[10];
            const ulonglong2* ep = reinterpret_cast<const ulonglong2*>(&sxe[i8][8 * pg]);
            const ulonglong2* op = reinterpret_cast<const ulonglong2*>(&sxo[i8][8 * pg]);
            #pragma unroll
            for (int q = 0; q < 5; q++) {
                ulonglong2 ve = ep[q]; e[2 * q] = ve.x; e[2 * q + 1] = ve.y;
                ulonglong2 vo = op[q]; o[2 * q] = vo.x; o[2 * q + 1] = vo.y;
            }
            #pragma unroll
            for (int oo = 0; oo < 4; oo++) {
                int ol = 4 * ocg + oo;
                float w0 = swt[ic * 5 + 0][ol];
                float w1 = swt[ic * 5 + 1][ol];
                float w2 = swt[ic * 5 + 2][ol];
                float w3 = swt[ic * 5 + 3][ol];
                float w4 = swt[ic * 5 + 4][ol];
                ull wd0 = pk2(w0, w0), wd1 = pk2(w1, w1), wd2 = pk2(w2, w2);
                ull wd3 = pk2(w3, w3), wd4 = pk2(w4, w4);
                #pragma unroll
                for (int j = 0; j < 8; j++) {
                    ull a = acc[oo][j];
                    a = fma2(e[j],     wd0, a);
                    a = fma2(o[j],     wd1, a);
                    a = fma2(e[j + 1], wd2, a);
                    a = fma2(o[j + 1], wd3, a);
                    a = fma2(e[j + 2], wd4, a);
                    acc[oo][j] = a;
                }
            }
        }
    }

    #pragma unroll
    for (int oo = 0; oo < 4; oo++) {
        int oc = oc0 + 4 * ocg + oo;
        float bb = bc2[oc];
        float gg = gc2[oc] * INV_BN;
        float be = bec2[oc];
        #pragma unroll
        for (int j = 0; j < 8; j++) {
            float2 a = upk2(acc[oo][j]);
            float r = fmaxf(fmaxf(fmaf(a.x + bb, gg, be), fmaf(a.y + bb, gg, be)), 0.f);
            int p = p0 + 8 * pg + j;
            if (p < 250) g_pool2[(b * 64 + oc) * 250 + p] = r;
        }
    }
}

// ---------------------------------------------------------------------------
// K5: conv3 K-split GEMM: part[ks][b][oc] = sum_{k in 64-chunk} X[b][k]*W[oc][k]
// grid 250 K-splits, 256 threads. REGISTER-STAGED loads: all 48 LDGs per
// thread issued before any STS (MLP ~48, vs ~1-2 for the rolled loop).
// f32x2 lanes = adjacent batch pair; thread tile 8 b x 4 oc, oc strided 32.
// ---------------------------------------------------------------------------
__global__ void __launch_bounds__(256) k_conv3(const float* __restrict__ Wc3) {
    int ks = blockIdx.x;       // 0..249
    int t = threadIdx.x;
    __shared__ __align__(16) float Xs[64][68];   // [kk][b], pad 68 (16B-aligned rows)
    __shared__ float Ws[64][133];                // [kk][oc], pad 133 (conflict-free)
    int og = t & 31;           // oc = og + 32*o, o=0..3
    int bg = t >> 5;           // warp id -> b0 = 8*bg (x loads warp-broadcast)
    int k0 = ks * 64;

    // ---- staged loads: issue ALL LDGs, then ALL STSs ----
    {
        float rw0[16], rw1[16], rx[16];
        #pragma unroll
        for (int j = 0; j < 16; j++) {
            int i = t + j * 256;
            rw0[j] = Wc3[(i >> 6) * 16000 + k0 + (i & 63)];
        }
        #pragma unroll
        for (int j = 0; j < 16; j++) {
            int i = t + (j + 16) * 256;
            rw1[j] = Wc3[(i >> 6) * 16000 + k0 + (i & 63)];
        }
        #pragma unroll
        for (int j = 0; j < 16; j++) {
            int i = t + j * 256;
            rx[j] = g_pool2[(i >> 6) * 16000 + k0 + (i & 63)];
        }
        #pragma unroll
        for (int j = 0; j < 16; j++) {
            int i = t + j * 256;
            Ws[i & 63][i >> 6] = rw0[j];
        }
        #pragma unroll
        for (int j = 0; j < 16; j++) {
            int i = t + (j + 16) * 256;
            Ws[i & 63][i >> 6] = rw1[j];
        }
        #pragma unroll
        for (int j = 0; j < 16; j++) {
            int i = t + j * 256;
            Xs[i & 63][i >> 6] = rx[j];
        }
    }
    __syncthreads();

    ull acc[4][4];
    #pragma unroll
    for (int o = 0; o < 4; o++)
        #pragma unroll
        for (int j = 0; j < 4; j++) acc[o][j] = 0ull;

    #pragma unroll 4
    for (int kk = 0; kk < 64; kk++) {
        const ull* xq = reinterpret_cast<const ull*>(&Xs[kk][8 * bg]);
        ull x0 = xq[0], x1 = xq[1], x2 = xq[2], x3 = xq[3];
        #pragma unroll
        for (int o = 0; o < 4; o++) {
            float wv = Ws[kk][og + 32 * o];
            ull wd = pk2(wv, wv);
            acc[o][0] = fma2(x0, wd, acc[o][0]);
            acc[o][1] = fma2(x1, wd, acc[o][1]);
            acc[o][2] = fma2(x2, wd, acc[o][2]);
            acc[o][3] = fma2(x3, wd, acc[o][3]);
        }
    }

    #pragma unroll
    for (int o = 0; o < 4; o++) {
        int oc = og + 32 * o;
        #pragma unroll
        for (int j = 0; j < 4; j++) {
            float2 v = upk2(acc[o][j]);
            int bb = 8 * bg + 2 * j;
            g_part3[(ks * 64 + bb) * 128 + oc]     = v.x;
            g_part3[(ks * 64 + bb + 1) * 128 + oc] = v.y;
        }
    }
}

// ---------------------------------------------------------------------------
// K6: reduce partials (+bc3) with 4-way split-K, FC 128->64 (+bn relu),
// FC 64->12, log_softmax. one block per batch, 512 threads.
// ---------------------------------------------------------------------------
__global__ void __launch_bounds__(512) k_fc(
        const float* __restrict__ bc3, const float* __restrict__ Wf,
        const float* __restrict__ bf, const float* __restrict__ gf,
        const float* __restrict__ bef, const float* __restrict__ Wo,
        const float* __restrict__ bo, float* __restrict__ out) {
    int b = blockIdx.x;
    int t = threadIdx.x;
    __shared__ float red[4][128];
    __shared__ float f[128], u[64], o[12];
    {
        int oc = t & 127, r = t >> 7;      // r = 0..3
        float s = 0.f;
        #pragma unroll 8
        for (int ks = r; ks < 250; ks += 4)
            s += g_part3[(ks * 64 + b) * 128 + oc];
        red[r][oc] = s;
    }
    __syncthreads();
    if (t < 128) f[t] = bc3[t] + ((red[0][t] + red[1][t]) + (red[2][t] + red[3][t]));
    __syncthreads();
    if (t < 64) {
        float z = bf[t];
        #pragma unroll 8
        for (int k = 0; k < 128; k++) z = fmaf(f[k], Wf[k * 64 + t], z);
        z = z * (INV_BN * gf[t]) + bef[t];
        u[t] = fmaxf(z, 0.f);
    }
    __syncthreads();
    if (t < 12) {
        float z = bo[t];
        #pragma unroll 8
        for (int k = 0; k < 64; k++) z = fmaf(u[k], Wo[k * 12 + t], z);
        o[t] = z;
    }
    __syncthreads();
    if (t < 12) {
        float m = o[0];
        #pragma unroll
        for (int i = 1; i < 12; i++) m = fmaxf(m, o[i]);
        float s = 0.f;
        #pragma unroll
        for (int i = 0; i < 12; i++) s += expf(o[i] - m);
        out[b * 12 + t] = (o[t] - m) - logf(s);
    }
}

// ---------------------------------------------------------------------------
extern "C" void kernel_launch(void* const* d_in, const int* in_sizes, int n_in,
                              void* d_out, int out_size) {
    const float* x_sample = (const float*)d_in[0];
    const float* x_graph  = (const float*)d_in[1];
    const float* W1   = (const float*)d_in[2];
    const float* b1   = (const float*)d_in[3];
    const float* gl   = (const float*)d_in[4];
    const float* bl   = (const float*)d_in[5];
    const float* Wg   = (const float*)d_in[6];
    const float* bg   = (const float*)d_in[7];
    const float* g1   = (const float*)d_in[8];
    const float* be1  = (const float*)d_in[9];
    const float* Wc1  = (const float*)d_in[10];
    const float* bc1  = (const float*)d_in[11];
    const float* gc1  = (const float*)d_in[12];
    const float* bec1 = (const float*)d_in[13];
    const float* Wc2  = (const float*)d_in[14];
    const float* bc2  = (const float*)d_in[15];
    const float* gc2  = (const float*)d_in[16];
    const float* bec2 = (const float*)d_in[17];
    const float* Wc3  = (const float*)d_in[18];
    const float* bc3  = (const float*)d_in[19];
    const float* Wf   = (const float*)d_in[20];
    const float* bf   = (const float*)d_in[21];
    const float* gf   = (const float*)d_in[22];
    const float* bef  = (const float*)d_in[23];
    const float* Wo   = (const float*)d_in[24];
    const float* bo   = (const float*)d_in[25];
    float* out = (float*)d_out;

    k_front<<<128, 1024>>>(x_sample, W1, b1, gl, bl, x_graph, Wg, bg, g1, be1);
    k_conv1<<<dim3(64, 4), 256>>>(Wc1, bc1, gc1, bec1);
    k_conv2<<<dim3(64, 4, 2), 64>>>(Wc2, bc2, gc2, bec2);
    k_conv3<<<250, 256>>>(Wc3);
    k_fc   <<<64, 512>>>(bc3, Wf, bf, gf, bef, Wo, bo, out);
}